// round 11
// baseline (speedup 1.0000x reference)
#include <cuda_runtime.h>
#include <cuda_bf16.h>

#define N_NODES   200000
#define N_EDGES   6400000
#define N_GRAPHS  512
#define DIM_IN    128
#define HID       32
#define BN_EPS    1e-5f

#define ENC_OFF   0
#define DEC_OFF   (N_NODES * HID)                     // 6,400,000
#define GLOB_OFF  (N_NODES * HID + N_NODES * DIM_IN)  // 32,000,000

#define FULLMASK  0xffffffffu
#define SCAN_BLOCKS 196
#define WSTRIDE   36                                  // 144B rows: 16B-aligned, conflict-free

// ---------------- scratch (device globals; no cudaMalloc allowed) ----------
__device__ int   g_cnt[N_NODES];
__device__ int   g_rowptr[N_NODES + 1];
__device__ int   g_cursor[N_NODES];
__device__ int   g_col[N_EDGES];
__device__ int   g_bsum[SCAN_BLOCKS];
__device__ int   g_boff[SCAN_BLOCKS];
__device__ int   g_goff[N_GRAPHS + 1];
__device__ float g_stats[10 * 64];                    // per layer: sum[32], sumsq[32]
__device__ __align__(16) float g_xp[N_NODES * HID];   // projected layer-0 input
__device__ __align__(16) float g_bufA[N_NODES * HID]; // ping
__device__ __align__(16) float g_bufC[N_NODES * HID]; // pong

// ---------------- setup kernels --------------------------------------------
__global__ void init_kernel() {
    int i = blockIdx.x * 256 + threadIdx.x;
    if (i < N_NODES) g_cnt[i] = 0;
    if (i < 10 * 64) g_stats[i] = 0.f;
}

__global__ void offsets_kernel(const int* __restrict__ batch) {
    int g = blockIdx.x * 256 + threadIdx.x;
    if (g > N_GRAPHS) return;
    if (g == N_GRAPHS) { g_goff[g] = N_NODES; return; }
    int lo = 0, hi = N_NODES;
    while (lo < hi) {
        int mid = (lo + hi) >> 1;
        if (batch[mid] < g) lo = mid + 1; else hi = mid;
    }
    g_goff[g] = lo;
}

__global__ void hist_kernel(const int* __restrict__ dst) {
    int e = blockIdx.x * 256 + threadIdx.x;   // exact: 25000*256 == N_EDGES
    atomicAdd(&g_cnt[dst[e]], 1);
}

// --- 3-phase exclusive scan of g_cnt -> g_rowptr / g_cursor ----------------
__global__ void scan_block_kernel() {      // SCAN_BLOCKS x 1024
    __shared__ int wtot[32];
    int tid = threadIdx.x, lane = tid & 31, wid = tid >> 5;
    int i = blockIdx.x * 1024 + tid;
    int v = (i < N_NODES) ? g_cnt[i] : 0;
    int incl = v;
    #pragma unroll
    for (int off = 1; off < 32; off <<= 1) {
        int t = __shfl_up_sync(FULLMASK, incl, off);
        if (lane >= off) incl += t;
    }
    if (lane == 31) wtot[wid] = incl;
    __syncthreads();
    if (wid == 0) {
        int wv = wtot[lane];
        #pragma unroll
        for (int off = 1; off < 32; off <<= 1) {
            int t = __shfl_up_sync(FULLMASK, wv, off);
            if (lane >= off) wv += t;
        }
        wtot[lane] = wv;
    }
    __syncthreads();
    int excl = (wid ? wtot[wid - 1] : 0) + incl - v;
    if (i < N_NODES) g_rowptr[i] = excl;
    if (tid == 1023) g_bsum[blockIdx.x] = wtot[31];
}

__global__ void scan_tops_kernel() {       // 1 x 256
    __shared__ int wt[8];
    int tid = threadIdx.x, lane = tid & 31, wid = tid >> 5;
    int v = (tid < SCAN_BLOCKS) ? g_bsum[tid] : 0;
    int incl = v;
    #pragma unroll
    for (int off = 1; off < 32; off <<= 1) {
        int t = __shfl_up_sync(FULLMASK, incl, off);
        if (lane >= off) incl += t;
    }
    if (lane == 31) wt[wid] = incl;
    __syncthreads();
    if (wid == 0) {
        int wv = (lane < 8) ? wt[lane] : 0;
        #pragma unroll
        for (int off = 1; off < 32; off <<= 1) {
            int t = __shfl_up_sync(FULLMASK, wv, off);
            if (lane >= off) wv += t;
        }
        if (lane < 8) wt[lane] = wv;
    }
    __syncthreads();
    int excl = (wid ? wt[wid - 1] : 0) + incl - v;
    if (tid < SCAN_BLOCKS) g_boff[tid] = excl;
}

__global__ void scan_add_kernel() {        // SCAN_BLOCKS x 1024
    int i = blockIdx.x * 1024 + threadIdx.x;
    if (i < N_NODES) {
        int r = g_rowptr[i] + g_boff[blockIdx.x];
        g_rowptr[i] = r;
        g_cursor[i] = r;
    }
    if (i == 0) g_rowptr[N_NODES] = N_EDGES;
}

__global__ void permute_kernel(const int* __restrict__ src, const int* __restrict__ dst) {
    int e = blockIdx.x * 256 + threadIdx.x;
    int d = dst[e];
    int p = atomicAdd(&g_cursor[d], 1);
    g_col[p] = src[e];
}

// ---------------- projection: xp = x @ e0_w1 (128 -> 32), GEMM-tiled -------
#define PROJ_SMEM ((128 * 132 + 128 * 32) * 4)
__global__ void __launch_bounds__(256) proj_kernel(const float* __restrict__ x,
                                                   const float* __restrict__ w1) {
    extern __shared__ float sm[];
    float* s_x = sm;               // stride 132 over k-rows
    float* s_w = sm + 128 * 132;
    int tid = threadIdx.x, lane = tid & 31, wrp = tid >> 5;
    int n0 = blockIdx.x * 128;

    for (int i = tid; i < 4096; i += 256) s_w[i] = w1[i];
    #pragma unroll
    for (int r = wrp; r < 128; r += 8) {
        int nn = n0 + r;
        const float* xr = x + (long long)nn * 128;
        #pragma unroll
        for (int c0 = 0; c0 < 128; c0 += 32) {
            float v = (nn < N_NODES) ? xr[c0 + lane] : 0.f;
            s_x[(c0 + lane) * 132 + r] = v;
        }
    }
    __syncthreads();

    int nb = (tid & 31) * 4, fb = (tid >> 5) * 4;
    float h[16];
    #pragma unroll
    for (int i = 0; i < 16; i++) h[i] = 0.f;
    #pragma unroll 4
    for (int k = 0; k < 128; k++) {
        float4 xv = *(const float4*)&s_x[k * 132 + nb];
        float4 wv = *(const float4*)&s_w[k * 32 + fb];
        h[0]  += xv.x * wv.x; h[1]  += xv.x * wv.y; h[2]  += xv.x * wv.z; h[3]  += xv.x * wv.w;
        h[4]  += xv.y * wv.x; h[5]  += xv.y * wv.y; h[6]  += xv.y * wv.z; h[7]  += xv.y * wv.w;
        h[8]  += xv.z * wv.x; h[9]  += xv.z * wv.y; h[10] += xv.z * wv.z; h[11] += xv.z * wv.w;
        h[12] += xv.w * wv.x; h[13] += xv.w * wv.y; h[14] += xv.w * wv.z; h[15] += xv.w * wv.w;
    }
    __syncthreads();
    #pragma unroll
    for (int ni = 0; ni < 4; ni++)
        #pragma unroll
        for (int fi = 0; fi < 4; fi++)
            s_x[(nb + ni) * 33 + fb + fi] = h[ni * 4 + fi];
    __syncthreads();
    #pragma unroll
    for (int r = wrp; r < 128; r += 8) {
        int nn = n0 + r;
        if (nn < N_NODES) g_xp[nn * 32 + lane] = s_x[r * 33 + lane];
    }
}

// ---------------- vectorized gather helper (unchanged from R9) -------------
__device__ __forceinline__ float gather_sum(const float* __restrict__ xin,
                                            int n, int start, int end,
                                            int lane) {
    const float4* x4 = (const float4*)xin;
    int c = lane & 7;
    int g = lane >> 3;
    float4 acc = make_float4(0.f, 0.f, 0.f, 0.f);
    if (g == 0) acc = x4[n * 8 + c];                 // self term, counted once
    for (int b0 = start; b0 < end; b0 += 32) {
        int nrem = end - b0;                         // >= 1
        int li = (lane < nrem) ? lane : 0;
        int idx = g_col[b0 + li];
        #pragma unroll
        for (int k = 0; k < 32; k += 4) {
            if (k < nrem) {
                int j = __shfl_sync(FULLMASK, idx, k + g);
                float4 v = x4[j * 8 + c];
                if (k + g < nrem) {
                    acc.x += v.x; acc.y += v.y; acc.z += v.z; acc.w += v.w;
                }
            }
        }
    }
    acc.x += __shfl_xor_sync(FULLMASK, acc.x, 8);
    acc.y += __shfl_xor_sync(FULLMASK, acc.y, 8);
    acc.z += __shfl_xor_sync(FULLMASK, acc.z, 8);
    acc.w += __shfl_xor_sync(FULLMASK, acc.w, 8);
    acc.x += __shfl_xor_sync(FULLMASK, acc.x, 16);
    acc.y += __shfl_xor_sync(FULLMASK, acc.y, 16);
    acc.z += __shfl_xor_sync(FULLMASK, acc.z, 16);
    acc.w += __shfl_xor_sync(FULLMASK, acc.w, 16);
    int srcl = lane >> 2;
    float tx = __shfl_sync(FULLMASK, acc.x, srcl);
    float ty = __shfl_sync(FULLMASK, acc.y, srcl);
    float tz = __shfl_sync(FULLMASK, acc.z, srcl);
    float tw = __shfl_sync(FULLMASK, acc.w, srcl);
    int comp = lane & 3;
    float t = (comp == 0) ? tx : (comp == 1) ? ty : (comp == 2) ? tz : tw;
    return t;
}

// ---------------- fused GIN: gather + BN-fold + float4-LDS MLP + stats -----
// t = bn_a*(self + sum_nb) + (deg+1)*bn_b ; out = relu(relu(t@w1+b1)@w2+b2)
template <bool HAS_BN, bool APPLY_W1>
__global__ void __launch_bounds__(256) gin_fused_kernel(
    const float* __restrict__ xin, float* __restrict__ outp,
    const float* __restrict__ w1, const float* __restrict__ b1,
    const float* __restrict__ w2, const float* __restrict__ b2,
    int sl_in, const float* __restrict__ gamma, const float* __restrict__ beta,
    int sl_out)
{
    // transposed weights: s_wXt[f_out*WSTRIDE + k]
    __shared__ __align__(16) float s_w1t[32 * WSTRIDE];
    __shared__ __align__(16) float s_w2t[32 * WSTRIDE];
    __shared__ __align__(16) float s_t[8 * WSTRIDE];   // per-warp staged vector
    __shared__ float sa[32], sb[32], s_b1[32], s_b2[32], s_sum[32], s_sq[32];
    int tid = threadIdx.x, lane = tid & 31, wrp = tid >> 5;

    if (APPLY_W1)
        for (int i = tid; i < 1024; i += 256) s_w1t[(i & 31) * WSTRIDE + (i >> 5)] = w1[i];
    for (int i = tid; i < 1024; i += 256) s_w2t[(i & 31) * WSTRIDE + (i >> 5)] = w2[i];
    if (tid < 32) {
        s_b1[tid] = b1[tid]; s_b2[tid] = b2[tid];
        s_sum[tid] = 0.f; s_sq[tid] = 0.f;
        if (HAS_BN) {
            float s = g_stats[sl_in * 64 + tid];
            float q = g_stats[sl_in * 64 + 32 + tid];
            const float invn = 1.f / (float)N_NODES;
            float m = s * invn;
            float v = fmaxf(q * invn - m * m, 0.f);
            float a = gamma[tid] * rsqrtf(v + BN_EPS);
            sa[tid] = a;
            sb[tid] = beta[tid] - a * m;
        }
    }
    __syncthreads();

    int n = blockIdx.x * 8 + wrp;
    int start = g_rowptr[n], end = g_rowptr[n + 1];

    float t = gather_sum(xin, n, start, end, lane);
    if (HAS_BN) t = sa[lane] * t + (float)(end - start + 1) * sb[lane];

    float* trow = &s_t[wrp * WSTRIDE];
    const float4* t4 = (const float4*)trow;

    float h1;
    if (APPLY_W1) {
        trow[lane] = t;
        __syncwarp();
        h1 = s_b1[lane];
        const float4* w4 = (const float4*)&s_w1t[lane * WSTRIDE];
        #pragma unroll
        for (int k4 = 0; k4 < 8; k4++) {
            float4 tv = t4[k4];
            float4 wv = w4[k4];
            h1 += tv.x * wv.x + tv.y * wv.y + tv.z * wv.z + tv.w * wv.w;
        }
        __syncwarp();
    } else {
        h1 = t + s_b1[lane];
    }
    h1 = fmaxf(h1, 0.f);

    trow[lane] = h1;
    __syncwarp();
    float h2 = s_b2[lane];
    {
        const float4* w4 = (const float4*)&s_w2t[lane * WSTRIDE];
        #pragma unroll
        for (int k4 = 0; k4 < 8; k4++) {
            float4 tv = t4[k4];
            float4 wv = w4[k4];
            h2 += tv.x * wv.x + tv.y * wv.y + tv.z * wv.z + tv.w * wv.w;
        }
    }
    h2 = fmaxf(h2, 0.f);

    outp[n * 32 + lane] = h2;

    atomicAdd(&s_sum[lane], h2);
    atomicAdd(&s_sq[lane], h2 * h2);
    __syncthreads();
    if (tid < 32)       atomicAdd(&g_stats[sl_out * 64 + tid], s_sum[tid]);
    else if (tid < 64)  atomicAdd(&g_stats[sl_out * 64 + tid], s_sq[tid - 32]);
}

// ---------------- final fused layer: gather + BN-fold + 32->32->128 --------
__global__ void __launch_bounds__(256) gin_last_fused_kernel(
    const float* __restrict__ xin, float* __restrict__ outp,
    const float* __restrict__ w1, const float* __restrict__ b1,
    const float* __restrict__ w2L, const float* __restrict__ b2L,
    int sl_in, const float* __restrict__ gamma, const float* __restrict__ beta)
{
    __shared__ __align__(16) float s_w1t[32 * WSTRIDE];
    __shared__ __align__(16) float s_wLt[128 * WSTRIDE];  // [f_out][k]
    __shared__ __align__(16) float s_t[8 * WSTRIDE];
    __shared__ float sa[32], sb[32], s_b1[32];
    int tid = threadIdx.x, lane = tid & 31, wrp = tid >> 5;

    for (int i = tid; i < 1024; i += 256) s_w1t[(i & 31) * WSTRIDE + (i >> 5)] = w1[i];
    for (int i = tid; i < 4096; i += 256) s_wLt[(i & 127) * WSTRIDE + (i >> 7)] = w2L[i];
    if (tid < 32) {
        s_b1[tid] = b1[tid];
        float s = g_stats[sl_in * 64 + tid];
        float q = g_stats[sl_in * 64 + 32 + tid];
        const float invn = 1.f / (float)N_NODES;
        float m = s * invn;
        float v = fmaxf(q * invn - m * m, 0.f);
        float a = gamma[tid] * rsqrtf(v + BN_EPS);
        sa[tid] = a;
        sb[tid] = beta[tid] - a * m;
    }
    __syncthreads();

    int n = blockIdx.x * 8 + wrp;
    int start = g_rowptr[n], end = g_rowptr[n + 1];

    float t = gather_sum(xin, n, start, end, lane);
    t = sa[lane] * t + (float)(end - start + 1) * sb[lane];

    float* trow = &s_t[wrp * WSTRIDE];
    const float4* t4 = (const float4*)trow;

    trow[lane] = t;
    __syncwarp();
    float h1 = s_b1[lane];
    {
        const float4* w4 = (const float4*)&s_w1t[lane * WSTRIDE];
        #pragma unroll
        for (int k4 = 0; k4 < 8; k4++) {
            float4 tv = t4[k4];
            float4 wv = w4[k4];
            h1 += tv.x * wv.x + tv.y * wv.y + tv.z * wv.z + tv.w * wv.w;
        }
    }
    h1 = fmaxf(h1, 0.f);
    __syncwarp();
    trow[lane] = h1;
    __syncwarp();

    float o0 = b2L[lane], o1 = b2L[32 + lane], o2 = b2L[64 + lane], o3 = b2L[96 + lane];
    {
        const float4* wa = (const float4*)&s_wLt[lane * WSTRIDE];
        const float4* wb = (const float4*)&s_wLt[(lane + 32) * WSTRIDE];
        const float4* wc = (const float4*)&s_wLt[(lane + 64) * WSTRIDE];
        const float4* wd = (const float4*)&s_wLt[(lane + 96) * WSTRIDE];
        #pragma unroll
        for (int k4 = 0; k4 < 8; k4++) {
            float4 hv = t4[k4];
            float4 va = wa[k4];
            float4 vb = wb[k4];
            float4 vc = wc[k4];
            float4 vd = wd[k4];
            o0 += hv.x * va.x + hv.y * va.y + hv.z * va.z + hv.w * va.w;
            o1 += hv.x * vb.x + hv.y * vb.y + hv.z * vb.z + hv.w * vb.w;
            o2 += hv.x * vc.x + hv.y * vc.y + hv.z * vc.z + hv.w * vc.w;
            o3 += hv.x * vd.x + hv.y * vd.y + hv.z * vd.z + hv.w * vd.w;
        }
    }
    float* orow = outp + (long long)n * 128;
    orow[lane]      = fmaxf(o0, 0.f);
    orow[32 + lane] = fmaxf(o1, 0.f);
    orow[64 + lane] = fmaxf(o2, 0.f);
    orow[96 + lane] = fmaxf(o3, 0.f);
}

// ---------------- BN apply (final encoder output only) ---------------------
__global__ void __launch_bounds__(256) bn_out_kernel(
    const float* __restrict__ pre, float* __restrict__ outp, int sl,
    const float* __restrict__ gamma, const float* __restrict__ beta)
{
    __shared__ float sa[32], sb[32];
    if (threadIdx.x < 32) {
        float s = g_stats[sl * 64 + threadIdx.x];
        float q = g_stats[sl * 64 + 32 + threadIdx.x];
        const float invn = 1.f / (float)N_NODES;
        float m = s * invn;
        float v = fmaxf(q * invn - m * m, 0.f);
        float a = gamma[threadIdx.x] * rsqrtf(v + BN_EPS);
        sa[threadIdx.x] = a;
        sb[threadIdx.x] = beta[threadIdx.x] - a * m;
    }
    __syncthreads();
    int i = blockIdx.x * 256 + threadIdx.x;     // float4 index; exact coverage
    int f0 = (i & 7) * 4;
    float4 v4 = ((const float4*)pre)[i];
    v4.x = sa[f0]     * v4.x + sb[f0];
    v4.y = sa[f0 + 1] * v4.y + sb[f0 + 1];
    v4.z = sa[f0 + 2] * v4.z + sb[f0 + 2];
    v4.w = sa[f0 + 3] * v4.w + sb[f0 + 3];
    ((float4*)outp)[i] = v4;
}

// ---------------- pool of post-BN layer rep (affine of raw pool) -----------
__global__ void __launch_bounds__(256) pool_kernel(
    const float* __restrict__ src, float* __restrict__ dst, int layer, int sl,
    const float* __restrict__ gamma, const float* __restrict__ beta)
{
    __shared__ float sa[32], sb2[32];
    __shared__ float sp[256];
    int tid = threadIdx.x;
    if (tid < 32) {
        float s = g_stats[sl * 64 + tid];
        float q = g_stats[sl * 64 + 32 + tid];
        const float invn = 1.f / (float)N_NODES;
        float m = s * invn;
        float v = fmaxf(q * invn - m * m, 0.f);
        float a = gamma[tid] * rsqrtf(v + BN_EPS);
        sa[tid] = a;
        sb2[tid] = beta[tid] - a * m;
    }
    __syncthreads();
    int g = blockIdx.x;
    int s = g_goff[g], e = g_goff[g + 1];
    int f = tid & 31, sub = tid >> 5;
    float p = 0.f;
    for (int r = s + sub; r < e; r += 8) p += src[r * 32 + f];
    sp[tid] = p;
    __syncthreads();
    if (tid < 32) {
        float t = sp[f];
        #pragma unroll
        for (int j = 1; j < 8; j++) t += sp[j * 32 + f];
        dst[g * (5 * HID) + layer * HID + f] = sa[f] * t + (float)(e - s) * sb2[f];
    }
}

// ---------------- launch ---------------------------------------------------
extern "C" void kernel_launch(void* const* d_in, const int* in_sizes, int n_in,
                              void* d_out, int out_size) {
    const float* x        = (const float*)d_in[0];
    const int*   ei       = (const int*)d_in[1];
    const int*   batch    = (const int*)d_in[2];
    const float* e0_w1    = (const float*)d_in[3];
    const float* e0_b1    = (const float*)d_in[4];
    const float* e0_w2    = (const float*)d_in[5];
    const float* e0_b2    = (const float*)d_in[6];
    const float* enc_w1   = (const float*)d_in[7];
    const float* enc_b1   = (const float*)d_in[8];
    const float* enc_w2   = (const float*)d_in[9];
    const float* enc_b2   = (const float*)d_in[10];
    const float* enc_gamma= (const float*)d_in[11];
    const float* enc_beta = (const float*)d_in[12];
    const float* dec_w1   = (const float*)d_in[13];
    const float* dec_b1   = (const float*)d_in[14];
    const float* dec_w2   = (const float*)d_in[15];
    const float* dec_b2   = (const float*)d_in[16];
    const float* dec_w2_last = (const float*)d_in[17];
    const float* dec_b2_last = (const float*)d_in[18];
    const float* dec_gamma= (const float*)d_in[19];
    const float* dec_beta = (const float*)d_in[20];
    float* out = (float*)d_out;

    const int* srcp = ei;
    const int* dstp = ei + N_EDGES;

    float *pA, *pC, *pXP;
    cudaGetSymbolAddress((void**)&pA,  g_bufA);
    cudaGetSymbolAddress((void**)&pC,  g_bufC);
    cudaGetSymbolAddress((void**)&pXP, g_xp);

    static int s_attr_done = 0;
    if (!s_attr_done) {
        cudaFuncSetAttribute(proj_kernel,
            cudaFuncAttributeMaxDynamicSharedMemorySize, PROJ_SMEM);
        s_attr_done = 1;
    }

    // CSR build + projection
    init_kernel<<<782, 256>>>();
    hist_kernel<<<25000, 256>>>(dstp);
    scan_block_kernel<<<SCAN_BLOCKS, 1024>>>();
    proj_kernel<<<1563, 256, PROJ_SMEM>>>(x, e0_w1);  // launch index 3 (ncu slot)
    scan_tops_kernel<<<1, 256>>>();
    scan_add_kernel<<<SCAN_BLOCKS, 1024>>>();
    offsets_kernel<<<3, 256>>>(batch);
    permute_kernel<<<25000, 256>>>(srcp, dstp);

    float* cur = pXP;
    float* nxt = pA;
    float* alt = pC;

    // ----- encoder (BN folded into next layer's aggregation + pool) -----
    gin_fused_kernel<false, false><<<25000, 256>>>(cur, nxt, nullptr,
        e0_b1, e0_w2, e0_b2, 0, nullptr, nullptr, 0);
    cur = nxt; nxt = alt; alt = cur;   // cur=A, nxt=C
    pool_kernel<<<N_GRAPHS, 256>>>(cur, out + GLOB_OFF, 0, 0, enc_gamma, enc_beta);
    for (int L = 1; L < 5; L++) {
        gin_fused_kernel<true, true><<<25000, 256>>>(cur, nxt,
            enc_w1 + (L - 1) * 1024, enc_b1 + (L - 1) * 32,
            enc_w2 + (L - 1) * 1024, enc_b2 + (L - 1) * 32,
            L - 1, enc_gamma + (L - 1) * 32, enc_beta + (L - 1) * 32, L);
        { float* t = cur; cur = nxt; nxt = t; }
        pool_kernel<<<N_GRAPHS, 256>>>(cur, out + GLOB_OFF, L, L,
            enc_gamma + L * 32, enc_beta + L * 32);
    }
    bn_out_kernel<<<6250, 256>>>(cur, out + ENC_OFF, 4, enc_gamma + 4 * 32, enc_beta + 4 * 32);

    // ----- decoder -----
    for (int L = 0; L < 4; L++) {
        const float* gI = (L == 0) ? (enc_gamma + 4 * 32) : (dec_gamma + (L - 1) * 32);
        const float* bI = (L == 0) ? (enc_beta  + 4 * 32) : (dec_beta  + (L - 1) * 32);
        int slin = (L == 0) ? 4 : (4 + L);
        gin_fused_kernel<true, true><<<25000, 256>>>(cur, nxt,
            dec_w1 + L * 1024, dec_b1 + L * 32,
            dec_w2 + L * 1024, dec_b2 + L * 32,
            slin, gI, bI, 5 + L);
        { float* t = cur; cur = nxt; nxt = t; }
    }
    gin_last_fused_kernel<<<25000, 256>>>(cur, out + DEC_OFF,
        dec_w1 + 4 * 1024, dec_b1 + 4 * 32, dec_w2_last, dec_b2_last,
        8, dec_gamma + 3 * 32, dec_beta + 3 * 32);
}

// round 12
// speedup vs baseline: 1.0509x; 1.0509x over previous
#include <cuda_runtime.h>
#include <cuda_bf16.h>

#define N_NODES   200000
#define N_EDGES   6400000
#define N_GRAPHS  512
#define DIM_IN    128
#define HID       32
#define BN_EPS    1e-5f

#define ENC_OFF   0
#define DEC_OFF   (N_NODES * HID)                     // 6,400,000
#define GLOB_OFF  (N_NODES * HID + N_NODES * DIM_IN)  // 32,000,000

#define FULLMASK  0xffffffffu
#define SCAN_BLOCKS 196

// ---------------- scratch (device globals; no cudaMalloc allowed) ----------
__device__ int   g_cnt[N_NODES];
__device__ int   g_rowptr[N_NODES + 1];
__device__ int   g_cursor[N_NODES];
__device__ int   g_col[N_EDGES];
__device__ int   g_bsum[SCAN_BLOCKS];
__device__ int   g_boff[SCAN_BLOCKS];
__device__ int   g_goff[N_GRAPHS + 1];
__device__ float g_stats[10 * 64];                    // per layer: sum[32], sumsq[32]
__device__ __align__(16) float g_xp[N_NODES * HID];   // projected layer-0 input
__device__ __align__(16) float g_bufA[N_NODES * HID]; // ping
__device__ __align__(16) float g_bufC[N_NODES * HID]; // pong

// ---------------- setup kernels --------------------------------------------
__global__ void init_kernel() {
    int i = blockIdx.x * 256 + threadIdx.x;
    if (i < N_NODES) g_cnt[i] = 0;
    if (i < 10 * 64) g_stats[i] = 0.f;
}

__global__ void offsets_kernel(const int* __restrict__ batch) {
    int g = blockIdx.x * 256 + threadIdx.x;
    if (g > N_GRAPHS) return;
    if (g == N_GRAPHS) { g_goff[g] = N_NODES; return; }
    int lo = 0, hi = N_NODES;
    while (lo < hi) {
        int mid = (lo + hi) >> 1;
        if (batch[mid] < g) lo = mid + 1; else hi = mid;
    }
    g_goff[g] = lo;
}

__global__ void hist_kernel(const int* __restrict__ dst) {
    int e4 = blockIdx.x * 256 + threadIdx.x;   // int4 index; 6250*256*4 == N_EDGES
    int4 d = ((const int4*)dst)[e4];
    atomicAdd(&g_cnt[d.x], 1);
    atomicAdd(&g_cnt[d.y], 1);
    atomicAdd(&g_cnt[d.z], 1);
    atomicAdd(&g_cnt[d.w], 1);
}

// --- 3-phase exclusive scan of g_cnt -> g_rowptr / g_cursor ----------------
__global__ void scan_block_kernel() {      // SCAN_BLOCKS x 1024
    __shared__ int wtot[32];
    int tid = threadIdx.x, lane = tid & 31, wid = tid >> 5;
    int i = blockIdx.x * 1024 + tid;
    int v = (i < N_NODES) ? g_cnt[i] : 0;
    int incl = v;
    #pragma unroll
    for (int off = 1; off < 32; off <<= 1) {
        int t = __shfl_up_sync(FULLMASK, incl, off);
        if (lane >= off) incl += t;
    }
    if (lane == 31) wtot[wid] = incl;
    __syncthreads();
    if (wid == 0) {
        int wv = wtot[lane];
        #pragma unroll
        for (int off = 1; off < 32; off <<= 1) {
            int t = __shfl_up_sync(FULLMASK, wv, off);
            if (lane >= off) wv += t;
        }
        wtot[lane] = wv;
    }
    __syncthreads();
    int excl = (wid ? wtot[wid - 1] : 0) + incl - v;
    if (i < N_NODES) g_rowptr[i] = excl;
    if (tid == 1023) g_bsum[blockIdx.x] = wtot[31];
}

__global__ void scan_tops_kernel() {       // 1 x 256
    __shared__ int wt[8];
    int tid = threadIdx.x, lane = tid & 31, wid = tid >> 5;
    int v = (tid < SCAN_BLOCKS) ? g_bsum[tid] : 0;
    int incl = v;
    #pragma unroll
    for (int off = 1; off < 32; off <<= 1) {
        int t = __shfl_up_sync(FULLMASK, incl, off);
        if (lane >= off) incl += t;
    }
    if (lane == 31) wt[wid] = incl;
    __syncthreads();
    if (wid == 0) {
        int wv = (lane < 8) ? wt[lane] : 0;
        #pragma unroll
        for (int off = 1; off < 32; off <<= 1) {
            int t = __shfl_up_sync(FULLMASK, wv, off);
            if (lane >= off) wv += t;
        }
        if (lane < 8) wt[lane] = wv;
    }
    __syncthreads();
    int excl = (wid ? wt[wid - 1] : 0) + incl - v;
    if (tid < SCAN_BLOCKS) g_boff[tid] = excl;
}

__global__ void scan_add_kernel() {        // SCAN_BLOCKS x 1024
    int i = blockIdx.x * 1024 + threadIdx.x;
    if (i < N_NODES) {
        int r = g_rowptr[i] + g_boff[blockIdx.x];
        g_rowptr[i] = r;
        g_cursor[i] = r;
    }
    if (i == 0) g_rowptr[N_NODES] = N_EDGES;
}

__global__ void permute_kernel(const int* __restrict__ src, const int* __restrict__ dst) {
    int e4 = blockIdx.x * 256 + threadIdx.x;   // int4 index; 6250*256*4 == N_EDGES
    int4 s = ((const int4*)src)[e4];
    int4 d = ((const int4*)dst)[e4];
    g_col[atomicAdd(&g_cursor[d.x], 1)] = s.x;
    g_col[atomicAdd(&g_cursor[d.y], 1)] = s.y;
    g_col[atomicAdd(&g_cursor[d.z], 1)] = s.z;
    g_col[atomicAdd(&g_cursor[d.w], 1)] = s.w;
}

// ---------------- projection: xp = x @ e0_w1 (128 -> 32), GEMM-tiled -------
#define PROJ_SMEM ((128 * 132 + 128 * 32) * 4)
__global__ void __launch_bounds__(256) proj_kernel(const float* __restrict__ x,
                                                   const float* __restrict__ w1) {
    extern __shared__ float sm[];
    float* s_x = sm;               // stride 132 over k-rows
    float* s_w = sm + 128 * 132;
    int tid = threadIdx.x, lane = tid & 31, wrp = tid >> 5;
    int n0 = blockIdx.x * 128;

    for (int i = tid; i < 4096; i += 256) s_w[i] = w1[i];
    #pragma unroll
    for (int r = wrp; r < 128; r += 8) {
        int nn = n0 + r;
        const float* xr = x + (long long)nn * 128;
        #pragma unroll
        for (int c0 = 0; c0 < 128; c0 += 32) {
            float v = (nn < N_NODES) ? xr[c0 + lane] : 0.f;
            s_x[(c0 + lane) * 132 + r] = v;
        }
    }
    __syncthreads();

    int nb = (tid & 31) * 4, fb = (tid >> 5) * 4;
    float h[16];
    #pragma unroll
    for (int i = 0; i < 16; i++) h[i] = 0.f;
    #pragma unroll 4
    for (int k = 0; k < 128; k++) {
        float4 xv = *(const float4*)&s_x[k * 132 + nb];
        float4 wv = *(const float4*)&s_w[k * 32 + fb];
        h[0]  += xv.x * wv.x; h[1]  += xv.x * wv.y; h[2]  += xv.x * wv.z; h[3]  += xv.x * wv.w;
        h[4]  += xv.y * wv.x; h[5]  += xv.y * wv.y; h[6]  += xv.y * wv.z; h[7]  += xv.y * wv.w;
        h[8]  += xv.z * wv.x; h[9]  += xv.z * wv.y; h[10] += xv.z * wv.z; h[11] += xv.z * wv.w;
        h[12] += xv.w * wv.x; h[13] += xv.w * wv.y; h[14] += xv.w * wv.z; h[15] += xv.w * wv.w;
    }
    __syncthreads();
    #pragma unroll
    for (int ni = 0; ni < 4; ni++)
        #pragma unroll
        for (int fi = 0; fi < 4; fi++)
            s_x[(nb + ni) * 33 + fb + fi] = h[ni * 4 + fi];
    __syncthreads();
    #pragma unroll
    for (int r = wrp; r < 128; r += 8) {
        int nn = n0 + r;
        if (nn < N_NODES) g_xp[nn * 32 + lane] = s_x[r * 33 + lane];
    }
}

// ---------------- vectorized gather helper (proven in R9) ------------------
__device__ __forceinline__ float gather_sum(const float* __restrict__ xin,
                                            int n, int start, int end,
                                            int lane) {
    const float4* x4 = (const float4*)xin;
    int c = lane & 7;
    int g = lane >> 3;
    float4 acc = make_float4(0.f, 0.f, 0.f, 0.f);
    if (g == 0) acc = x4[n * 8 + c];                 // self term, counted once
    for (int b0 = start; b0 < end; b0 += 32) {
        int nrem = end - b0;                         // >= 1
        int li = (lane < nrem) ? lane : 0;
        int idx = g_col[b0 + li];
        #pragma unroll
        for (int k = 0; k < 32; k += 4) {
            if (k < nrem) {
                int j = __shfl_sync(FULLMASK, idx, k + g);
                float4 v = x4[j * 8 + c];
                if (k + g < nrem) {
                    acc.x += v.x; acc.y += v.y; acc.z += v.z; acc.w += v.w;
                }
            }
        }
    }
    acc.x += __shfl_xor_sync(FULLMASK, acc.x, 8);
    acc.y += __shfl_xor_sync(FULLMASK, acc.y, 8);
    acc.z += __shfl_xor_sync(FULLMASK, acc.z, 8);
    acc.w += __shfl_xor_sync(FULLMASK, acc.w, 8);
    acc.x += __shfl_xor_sync(FULLMASK, acc.x, 16);
    acc.y += __shfl_xor_sync(FULLMASK, acc.y, 16);
    acc.z += __shfl_xor_sync(FULLMASK, acc.z, 16);
    acc.w += __shfl_xor_sync(FULLMASK, acc.w, 16);
    int srcl = lane >> 2;
    float tx = __shfl_sync(FULLMASK, acc.x, srcl);
    float ty = __shfl_sync(FULLMASK, acc.y, srcl);
    float tz = __shfl_sync(FULLMASK, acc.z, srcl);
    float tw = __shfl_sync(FULLMASK, acc.w, srcl);
    int comp = lane & 3;
    float t = (comp == 0) ? tx : (comp == 1) ? ty : (comp == 2) ? tz : tw;
    return t;
}

// ---------------- fused GIN: gather + BN-fold + shuffle-GEMV MLP + stats ---
// 512 threads = 16 nodes/block (halves per-block weight re-reads)
template <bool HAS_BN, bool APPLY_W1>
__global__ void __launch_bounds__(512) gin_fused_kernel(
    const float* __restrict__ xin, float* __restrict__ outp,
    const float* __restrict__ w1, const float* __restrict__ b1,
    const float* __restrict__ w2, const float* __restrict__ b2,
    int sl_in, const float* __restrict__ gamma, const float* __restrict__ beta,
    int sl_out)
{
    __shared__ float s_w1[1024], s_w2[1024];
    __shared__ float sa[32], sb[32], s_b1[32], s_b2[32], s_sum[32], s_sq[32];
    int tid = threadIdx.x, lane = tid & 31, wrp = tid >> 5;

    if (APPLY_W1) for (int i = tid; i < 1024; i += 512) s_w1[i] = w1[i];
    for (int i = tid; i < 1024; i += 512) s_w2[i] = w2[i];
    if (tid < 32) {
        s_b1[tid] = b1[tid]; s_b2[tid] = b2[tid];
        s_sum[tid] = 0.f; s_sq[tid] = 0.f;
        if (HAS_BN) {
            float s = g_stats[sl_in * 64 + tid];
            float q = g_stats[sl_in * 64 + 32 + tid];
            const float invn = 1.f / (float)N_NODES;
            float m = s * invn;
            float v = fmaxf(q * invn - m * m, 0.f);
            float a = gamma[tid] * rsqrtf(v + BN_EPS);
            sa[tid] = a;
            sb[tid] = beta[tid] - a * m;
        }
    }
    __syncthreads();

    int n = blockIdx.x * 16 + wrp;
    int start = g_rowptr[n], end = g_rowptr[n + 1];

    float t = gather_sum(xin, n, start, end, lane);
    if (HAS_BN) t = sa[lane] * t + (float)(end - start + 1) * sb[lane];

    float h1;
    if (APPLY_W1) {
        h1 = s_b1[lane];
        #pragma unroll
        for (int k = 0; k < 32; k++) h1 += __shfl_sync(FULLMASK, t, k) * s_w1[k * 32 + lane];
    } else {
        h1 = t + s_b1[lane];
    }
    h1 = fmaxf(h1, 0.f);

    float h2 = s_b2[lane];
    #pragma unroll
    for (int k = 0; k < 32; k++) h2 += __shfl_sync(FULLMASK, h1, k) * s_w2[k * 32 + lane];
    h2 = fmaxf(h2, 0.f);

    outp[n * 32 + lane] = h2;

    atomicAdd(&s_sum[lane], h2);
    atomicAdd(&s_sq[lane], h2 * h2);
    __syncthreads();
    if (tid < 32)       atomicAdd(&g_stats[sl_out * 64 + tid], s_sum[tid]);
    else if (tid < 64)  atomicAdd(&g_stats[sl_out * 64 + tid], s_sq[tid - 32]);
}

// ---------------- final fused layer: gather + BN-fold + 32->32->128 --------
__global__ void __launch_bounds__(512) gin_last_fused_kernel(
    const float* __restrict__ xin, float* __restrict__ outp,
    const float* __restrict__ w1, const float* __restrict__ b1,
    const float* __restrict__ w2L, const float* __restrict__ b2L,
    int sl_in, const float* __restrict__ gamma, const float* __restrict__ beta)
{
    __shared__ float s_w1[1024];
    __shared__ float wLs[HID * DIM_IN];
    __shared__ float sa[32], sb[32], s_b1[32];
    int tid = threadIdx.x, lane = tid & 31, wrp = tid >> 5;

    for (int i = tid; i < 1024; i += 512) s_w1[i] = w1[i];
    for (int i = tid; i < HID * DIM_IN; i += 512) wLs[i] = w2L[i];
    if (tid < 32) {
        s_b1[tid] = b1[tid];
        float s = g_stats[sl_in * 64 + tid];
        float q = g_stats[sl_in * 64 + 32 + tid];
        const float invn = 1.f / (float)N_NODES;
        float m = s * invn;
        float v = fmaxf(q * invn - m * m, 0.f);
        float a = gamma[tid] * rsqrtf(v + BN_EPS);
        sa[tid] = a;
        sb[tid] = beta[tid] - a * m;
    }
    __syncthreads();

    int n = blockIdx.x * 16 + wrp;
    int start = g_rowptr[n], end = g_rowptr[n + 1];

    float t = gather_sum(xin, n, start, end, lane);
    t = sa[lane] * t + (float)(end - start + 1) * sb[lane];

    float h1 = s_b1[lane];
    #pragma unroll
    for (int k = 0; k < 32; k++) h1 += __shfl_sync(FULLMASK, t, k) * s_w1[k * 32 + lane];
    h1 = fmaxf(h1, 0.f);

    float o0 = b2L[lane], o1 = b2L[32 + lane], o2 = b2L[64 + lane], o3 = b2L[96 + lane];
    #pragma unroll
    for (int k = 0; k < 32; k++) {
        float hk = __shfl_sync(FULLMASK, h1, k);
        const float* wr = &wLs[k * 128];
        o0 += hk * wr[lane];
        o1 += hk * wr[32 + lane];
        o2 += hk * wr[64 + lane];
        o3 += hk * wr[96 + lane];
    }
    float* orow = outp + (long long)n * 128;
    orow[lane]      = fmaxf(o0, 0.f);
    orow[32 + lane] = fmaxf(o1, 0.f);
    orow[64 + lane] = fmaxf(o2, 0.f);
    orow[96 + lane] = fmaxf(o3, 0.f);
}

// ---------------- BN apply (final encoder output only) ---------------------
__global__ void __launch_bounds__(256) bn_out_kernel(
    const float* __restrict__ pre, float* __restrict__ outp, int sl,
    const float* __restrict__ gamma, const float* __restrict__ beta)
{
    __shared__ float sa[32], sb[32];
    if (threadIdx.x < 32) {
        float s = g_stats[sl * 64 + threadIdx.x];
        float q = g_stats[sl * 64 + 32 + threadIdx.x];
        const float invn = 1.f / (float)N_NODES;
        float m = s * invn;
        float v = fmaxf(q * invn - m * m, 0.f);
        float a = gamma[threadIdx.x] * rsqrtf(v + BN_EPS);
        sa[threadIdx.x] = a;
        sb[threadIdx.x] = beta[threadIdx.x] - a * m;
    }
    __syncthreads();
    int i = blockIdx.x * 256 + threadIdx.x;     // float4 index; exact coverage
    int f0 = (i & 7) * 4;
    float4 v4 = ((const float4*)pre)[i];
    v4.x = sa[f0]     * v4.x + sb[f0];
    v4.y = sa[f0 + 1] * v4.y + sb[f0 + 1];
    v4.z = sa[f0 + 2] * v4.z + sb[f0 + 2];
    v4.w = sa[f0 + 3] * v4.w + sb[f0 + 3];
    ((float4*)outp)[i] = v4;
}

// ---------------- pool of post-BN layer rep (affine of raw pool) -----------
__global__ void __launch_bounds__(256) pool_kernel(
    const float* __restrict__ src, float* __restrict__ dst, int layer, int sl,
    const float* __restrict__ gamma, const float* __restrict__ beta)
{
    __shared__ float sa[32], sb2[32];
    __shared__ float sp[256];
    int tid = threadIdx.x;
    if (tid < 32) {
        float s = g_stats[sl * 64 + tid];
        float q = g_stats[sl * 64 + 32 + tid];
        const float invn = 1.f / (float)N_NODES;
        float m = s * invn;
        float v = fmaxf(q * invn - m * m, 0.f);
        float a = gamma[tid] * rsqrtf(v + BN_EPS);
        sa[tid] = a;
        sb2[tid] = beta[tid] - a * m;
    }
    __syncthreads();
    int g = blockIdx.x;
    int s = g_goff[g], e = g_goff[g + 1];
    int f = tid & 31, sub = tid >> 5;
    float p = 0.f;
    for (int r = s + sub; r < e; r += 8) p += src[r * 32 + f];
    sp[tid] = p;
    __syncthreads();
    if (tid < 32) {
        float t = sp[f];
        #pragma unroll
        for (int j = 1; j < 8; j++) t += sp[j * 32 + f];
        dst[g * (5 * HID) + layer * HID + f] = sa[f] * t + (float)(e - s) * sb2[f];
    }
}

// ---------------- launch ---------------------------------------------------
extern "C" void kernel_launch(void* const* d_in, const int* in_sizes, int n_in,
                              void* d_out, int out_size) {
    const float* x        = (const float*)d_in[0];
    const int*   ei       = (const int*)d_in[1];
    const int*   batch    = (const int*)d_in[2];
    const float* e0_w1    = (const float*)d_in[3];
    const float* e0_b1    = (const float*)d_in[4];
    const float* e0_w2    = (const float*)d_in[5];
    const float* e0_b2    = (const float*)d_in[6];
    const float* enc_w1   = (const float*)d_in[7];
    const float* enc_b1   = (const float*)d_in[8];
    const float* enc_w2   = (const float*)d_in[9];
    const float* enc_b2   = (const float*)d_in[10];
    const float* enc_gamma= (const float*)d_in[11];
    const float* enc_beta = (const float*)d_in[12];
    const float* dec_w1   = (const float*)d_in[13];
    const float* dec_b1   = (const float*)d_in[14];
    const float* dec_w2   = (const float*)d_in[15];
    const float* dec_b2   = (const float*)d_in[16];
    const float* dec_w2_last = (const float*)d_in[17];
    const float* dec_b2_last = (const float*)d_in[18];
    const float* dec_gamma= (const float*)d_in[19];
    const float* dec_beta = (const float*)d_in[20];
    float* out = (float*)d_out;

    const int* srcp = ei;
    const int* dstp = ei + N_EDGES;

    float *pA, *pC, *pXP;
    cudaGetSymbolAddress((void**)&pA,  g_bufA);
    cudaGetSymbolAddress((void**)&pC,  g_bufC);
    cudaGetSymbolAddress((void**)&pXP, g_xp);

    static int s_attr_done = 0;
    if (!s_attr_done) {
        cudaFuncSetAttribute(proj_kernel,
            cudaFuncAttributeMaxDynamicSharedMemorySize, PROJ_SMEM);
        s_attr_done = 1;
    }

    // CSR build + projection
    init_kernel<<<782, 256>>>();
    hist_kernel<<<6250, 256>>>(dstp);
    scan_block_kernel<<<SCAN_BLOCKS, 1024>>>();
    proj_kernel<<<1563, 256, PROJ_SMEM>>>(x, e0_w1);  // launch index 3 (ncu slot)
    scan_tops_kernel<<<1, 256>>>();
    scan_add_kernel<<<SCAN_BLOCKS, 1024>>>();
    offsets_kernel<<<3, 256>>>(batch);
    permute_kernel<<<6250, 256>>>(srcp, dstp);

    float* cur = pXP;
    float* nxt = pA;
    float* alt = pC;

    // ----- encoder (BN folded into next layer's aggregation + pool) -----
    gin_fused_kernel<false, false><<<12500, 512>>>(cur, nxt, nullptr,
        e0_b1, e0_w2, e0_b2, 0, nullptr, nullptr, 0);
    cur = nxt; nxt = alt; alt = cur;   // cur=A, nxt=C
    pool_kernel<<<N_GRAPHS, 256>>>(cur, out + GLOB_OFF, 0, 0, enc_gamma, enc_beta);
    for (int L = 1; L < 5; L++) {
        gin_fused_kernel<true, true><<<12500, 512>>>(cur, nxt,
            enc_w1 + (L - 1) * 1024, enc_b1 + (L - 1) * 32,
            enc_w2 + (L - 1) * 1024, enc_b2 + (L - 1) * 32,
            L - 1, enc_gamma + (L - 1) * 32, enc_beta + (L - 1) * 32, L);
        { float* t = cur; cur = nxt; nxt = t; }
        pool_kernel<<<N_GRAPHS, 256>>>(cur, out + GLOB_OFF, L, L,
            enc_gamma + L * 32, enc_beta + L * 32);
    }
    bn_out_kernel<<<6250, 256>>>(cur, out + ENC_OFF, 4, enc_gamma + 4 * 32, enc_beta + 4 * 32);

    // ----- decoder -----
    for (int L = 0; L < 4; L++) {
        const float* gI = (L == 0) ? (enc_gamma + 4 * 32) : (dec_gamma + (L - 1) * 32);
        const float* bI = (L == 0) ? (enc_beta  + 4 * 32) : (dec_beta  + (L - 1) * 32);
        int slin = (L == 0) ? 4 : (4 + L);
        gin_fused_kernel<true, true><<<12500, 512>>>(cur, nxt,
            dec_w1 + L * 1024, dec_b1 + L * 32,
            dec_w2 + L * 1024, dec_b2 + L * 32,
            slin, gI, bI, 5 + L);
        { float* t = cur; cur = nxt; nxt = t; }
    }
    gin_last_fused_kernel<<<12500, 512>>>(cur, out + DEC_OFF,
        dec_w1 + 4 * 1024, dec_b1 + 4 * 32, dec_w2_last, dec_b2_last,
        8, dec_gamma + 3 * 32, dec_beta + 3 * 32);
}

// round 13
// speedup vs baseline: 1.0559x; 1.0048x over previous
#include <cuda_runtime.h>
#include <cuda_bf16.h>

#define N_NODES   200000
#define N_EDGES   6400000
#define N_GRAPHS  512
#define DIM_IN    128
#define HID       32
#define BN_EPS    1e-5f

#define ENC_OFF   0
#define DEC_OFF   (N_NODES * HID)                     // 6,400,000
#define GLOB_OFF  (N_NODES * HID + N_NODES * DIM_IN)  // 32,000,000

#define FULLMASK  0xffffffffu
#define SCAN_BLOCKS 196

// ---------------- scratch (device globals; no cudaMalloc allowed) ----------
__device__ int   g_cnt[N_NODES];
__device__ int   g_rowptr[N_NODES + 1];
__device__ int   g_cursor[N_NODES];
__device__ int   g_col[N_EDGES];
__device__ int   g_bsum[SCAN_BLOCKS];
__device__ int   g_boff[SCAN_BLOCKS];
__device__ int   g_goff[N_GRAPHS + 1];
__device__ float g_stats[10 * 64];                    // per layer: sum[32], sumsq[32]
__device__ float g_poolraw[5 * N_GRAPHS * 32];        // raw per-graph sums, enc layers
__device__ __align__(16) float g_xp[N_NODES * HID];   // projected layer-0 input
__device__ __align__(16) float g_bufA[N_NODES * HID]; // ping
__device__ __align__(16) float g_bufC[N_NODES * HID]; // pong

// ---------------- setup kernels --------------------------------------------
__global__ void init_kernel() {
    int i = blockIdx.x * 256 + threadIdx.x;
    if (i < N_NODES) g_cnt[i] = 0;
    if (i < 10 * 64) g_stats[i] = 0.f;
    if (i < 5 * N_GRAPHS * 32) g_poolraw[i] = 0.f;
}

__global__ void offsets_kernel(const int* __restrict__ batch) {
    int g = blockIdx.x * 256 + threadIdx.x;
    if (g > N_GRAPHS) return;
    if (g == N_GRAPHS) { g_goff[g] = N_NODES; return; }
    int lo = 0, hi = N_NODES;
    while (lo < hi) {
        int mid = (lo + hi) >> 1;
        if (batch[mid] < g) lo = mid + 1; else hi = mid;
    }
    g_goff[g] = lo;
}

__global__ void hist_kernel(const int* __restrict__ dst) {
    int e4 = blockIdx.x * 256 + threadIdx.x;   // int4 index; 6250*256*4 == N_EDGES
    int4 d = ((const int4*)dst)[e4];
    atomicAdd(&g_cnt[d.x], 1);
    atomicAdd(&g_cnt[d.y], 1);
    atomicAdd(&g_cnt[d.z], 1);
    atomicAdd(&g_cnt[d.w], 1);
}

// --- 3-phase exclusive scan of g_cnt -> g_rowptr / g_cursor ----------------
__global__ void scan_block_kernel() {      // SCAN_BLOCKS x 1024
    __shared__ int wtot[32];
    int tid = threadIdx.x, lane = tid & 31, wid = tid >> 5;
    int i = blockIdx.x * 1024 + tid;
    int v = (i < N_NODES) ? g_cnt[i] : 0;
    int incl = v;
    #pragma unroll
    for (int off = 1; off < 32; off <<= 1) {
        int t = __shfl_up_sync(FULLMASK, incl, off);
        if (lane >= off) incl += t;
    }
    if (lane == 31) wtot[wid] = incl;
    __syncthreads();
    if (wid == 0) {
        int wv = wtot[lane];
        #pragma unroll
        for (int off = 1; off < 32; off <<= 1) {
            int t = __shfl_up_sync(FULLMASK, wv, off);
            if (lane >= off) wv += t;
        }
        wtot[lane] = wv;
    }
    __syncthreads();
    int excl = (wid ? wtot[wid - 1] : 0) + incl - v;
    if (i < N_NODES) g_rowptr[i] = excl;
    if (tid == 1023) g_bsum[blockIdx.x] = wtot[31];
}

__global__ void scan_tops_kernel() {       // 1 x 256
    __shared__ int wt[8];
    int tid = threadIdx.x, lane = tid & 31, wid = tid >> 5;
    int v = (tid < SCAN_BLOCKS) ? g_bsum[tid] : 0;
    int incl = v;
    #pragma unroll
    for (int off = 1; off < 32; off <<= 1) {
        int t = __shfl_up_sync(FULLMASK, incl, off);
        if (lane >= off) incl += t;
    }
    if (lane == 31) wt[wid] = incl;
    __syncthreads();
    if (wid == 0) {
        int wv = (lane < 8) ? wt[lane] : 0;
        #pragma unroll
        for (int off = 1; off < 32; off <<= 1) {
            int t = __shfl_up_sync(FULLMASK, wv, off);
            if (lane >= off) wv += t;
        }
        if (lane < 8) wt[lane] = wv;
    }
    __syncthreads();
    int excl = (wid ? wt[wid - 1] : 0) + incl - v;
    if (tid < SCAN_BLOCKS) g_boff[tid] = excl;
}

__global__ void scan_add_kernel() {        // SCAN_BLOCKS x 1024
    int i = blockIdx.x * 1024 + threadIdx.x;
    if (i < N_NODES) {
        int r = g_rowptr[i] + g_boff[blockIdx.x];
        g_rowptr[i] = r;
        g_cursor[i] = r;
    }
    if (i == 0) g_rowptr[N_NODES] = N_EDGES;
}

__global__ void permute_kernel(const int* __restrict__ src, const int* __restrict__ dst) {
    int e4 = blockIdx.x * 256 + threadIdx.x;   // int4 index; 6250*256*4 == N_EDGES
    int4 s = ((const int4*)src)[e4];
    int4 d = ((const int4*)dst)[e4];
    g_col[atomicAdd(&g_cursor[d.x], 1)] = s.x;
    g_col[atomicAdd(&g_cursor[d.y], 1)] = s.y;
    g_col[atomicAdd(&g_cursor[d.z], 1)] = s.z;
    g_col[atomicAdd(&g_cursor[d.w], 1)] = s.w;
}

// ---------------- projection: xp = x @ e0_w1 (128 -> 32), GEMM-tiled -------
#define PROJ_SMEM ((128 * 132 + 128 * 32) * 4)
__global__ void __launch_bounds__(256) proj_kernel(const float* __restrict__ x,
                                                   const float* __restrict__ w1) {
    extern __shared__ float sm[];
    float* s_x = sm;               // stride 132 over k-rows
    float* s_w = sm + 128 * 132;
    int tid = threadIdx.x, lane = tid & 31, wrp = tid >> 5;
    int n0 = blockIdx.x * 128;

    for (int i = tid; i < 4096; i += 256) s_w[i] = w1[i];
    #pragma unroll
    for (int r = wrp; r < 128; r += 8) {
        int nn = n0 + r;
        const float* xr = x + (long long)nn * 128;
        #pragma unroll
        for (int c0 = 0; c0 < 128; c0 += 32) {
            float v = (nn < N_NODES) ? xr[c0 + lane] : 0.f;
            s_x[(c0 + lane) * 132 + r] = v;
        }
    }
    __syncthreads();

    int nb = (tid & 31) * 4, fb = (tid >> 5) * 4;
    float h[16];
    #pragma unroll
    for (int i = 0; i < 16; i++) h[i] = 0.f;
    #pragma unroll 4
    for (int k = 0; k < 128; k++) {
        float4 xv = *(const float4*)&s_x[k * 132 + nb];
        float4 wv = *(const float4*)&s_w[k * 32 + fb];
        h[0]  += xv.x * wv.x; h[1]  += xv.x * wv.y; h[2]  += xv.x * wv.z; h[3]  += xv.x * wv.w;
        h[4]  += xv.y * wv.x; h[5]  += xv.y * wv.y; h[6]  += xv.y * wv.z; h[7]  += xv.y * wv.w;
        h[8]  += xv.z * wv.x; h[9]  += xv.z * wv.y; h[10] += xv.z * wv.z; h[11] += xv.z * wv.w;
        h[12] += xv.w * wv.x; h[13] += xv.w * wv.y; h[14] += xv.w * wv.z; h[15] += xv.w * wv.w;
    }
    __syncthreads();
    #pragma unroll
    for (int ni = 0; ni < 4; ni++)
        #pragma unroll
        for (int fi = 0; fi < 4; fi++)
            s_x[(nb + ni) * 33 + fb + fi] = h[ni * 4 + fi];
    __syncthreads();
    #pragma unroll
    for (int r = wrp; r < 128; r += 8) {
        int nn = n0 + r;
        if (nn < N_NODES) g_xp[nn * 32 + lane] = s_x[r * 33 + lane];
    }
}

// ---------------- vectorized gather helper (proven in R9) ------------------
__device__ __forceinline__ float gather_sum(const float* __restrict__ xin,
                                            int n, int start, int end,
                                            int lane) {
    const float4* x4 = (const float4*)xin;
    int c = lane & 7;
    int g = lane >> 3;
    float4 acc = make_float4(0.f, 0.f, 0.f, 0.f);
    if (g == 0) acc = x4[n * 8 + c];                 // self term, counted once
    for (int b0 = start; b0 < end; b0 += 32) {
        int nrem = end - b0;                         // >= 1
        int li = (lane < nrem) ? lane : 0;
        int idx = g_col[b0 + li];
        #pragma unroll
        for (int k = 0; k < 32; k += 4) {
            if (k < nrem) {
                int j = __shfl_sync(FULLMASK, idx, k + g);
                float4 v = x4[j * 8 + c];
                if (k + g < nrem) {
                    acc.x += v.x; acc.y += v.y; acc.z += v.z; acc.w += v.w;
                }
            }
        }
    }
    acc.x += __shfl_xor_sync(FULLMASK, acc.x, 8);
    acc.y += __shfl_xor_sync(FULLMASK, acc.y, 8);
    acc.z += __shfl_xor_sync(FULLMASK, acc.z, 8);
    acc.w += __shfl_xor_sync(FULLMASK, acc.w, 8);
    acc.x += __shfl_xor_sync(FULLMASK, acc.x, 16);
    acc.y += __shfl_xor_sync(FULLMASK, acc.y, 16);
    acc.z += __shfl_xor_sync(FULLMASK, acc.z, 16);
    acc.w += __shfl_xor_sync(FULLMASK, acc.w, 16);
    int srcl = lane >> 2;
    float tx = __shfl_sync(FULLMASK, acc.x, srcl);
    float ty = __shfl_sync(FULLMASK, acc.y, srcl);
    float tz = __shfl_sync(FULLMASK, acc.z, srcl);
    float tw = __shfl_sync(FULLMASK, acc.w, srcl);
    int comp = lane & 3;
    float t = (comp == 0) ? tx : (comp == 1) ? ty : (comp == 2) ? tz : tw;
    return t;
}

// ---------------- fused GIN: gather + BN-fold + MLP + stats (+pool) --------
// 512 threads = 16 nodes/block; encoder layers also accumulate raw pool sums
template <bool HAS_BN, bool APPLY_W1, bool HAS_POOL>
__global__ void __launch_bounds__(512) gin_fused_kernel(
    const float* __restrict__ xin, float* __restrict__ outp,
    const float* __restrict__ w1, const float* __restrict__ b1,
    const float* __restrict__ w2, const float* __restrict__ b2,
    int sl_in, const float* __restrict__ gamma, const float* __restrict__ beta,
    int sl_out, const int* __restrict__ batchp, float* __restrict__ poolraw)
{
    __shared__ float s_w1[1024], s_w2[1024];
    __shared__ float sa[32], sb[32], s_b1[32], s_b2[32], s_sum[32], s_sq[32];
    __shared__ float s_pool[4 * 32];
    __shared__ int   s_gf;
    int tid = threadIdx.x, lane = tid & 31, wrp = tid >> 5;

    if (APPLY_W1) for (int i = tid; i < 1024; i += 512) s_w1[i] = w1[i];
    for (int i = tid; i < 1024; i += 512) s_w2[i] = w2[i];
    if (HAS_POOL) {
        if (tid < 128) s_pool[tid] = 0.f;
        if (tid == 0) s_gf = batchp[blockIdx.x * 16];
    }
    if (tid < 32) {
        s_b1[tid] = b1[tid]; s_b2[tid] = b2[tid];
        s_sum[tid] = 0.f; s_sq[tid] = 0.f;
        if (HAS_BN) {
            float s = g_stats[sl_in * 64 + tid];
            float q = g_stats[sl_in * 64 + 32 + tid];
            const float invn = 1.f / (float)N_NODES;
            float m = s * invn;
            float v = fmaxf(q * invn - m * m, 0.f);
            float a = gamma[tid] * rsqrtf(v + BN_EPS);
            sa[tid] = a;
            sb[tid] = beta[tid] - a * m;
        }
    }
    __syncthreads();

    int n = blockIdx.x * 16 + wrp;
    int start = g_rowptr[n], end = g_rowptr[n + 1];

    float t = gather_sum(xin, n, start, end, lane);
    if (HAS_BN) t = sa[lane] * t + (float)(end - start + 1) * sb[lane];

    float h1;
    if (APPLY_W1) {
        h1 = s_b1[lane];
        #pragma unroll
        for (int k = 0; k < 32; k++) h1 += __shfl_sync(FULLMASK, t, k) * s_w1[k * 32 + lane];
    } else {
        h1 = t + s_b1[lane];
    }
    h1 = fmaxf(h1, 0.f);

    float h2 = s_b2[lane];
    #pragma unroll
    for (int k = 0; k < 32; k++) h2 += __shfl_sync(FULLMASK, h1, k) * s_w2[k * 32 + lane];
    h2 = fmaxf(h2, 0.f);

    outp[n * 32 + lane] = h2;

    atomicAdd(&s_sum[lane], h2);
    atomicAdd(&s_sq[lane], h2 * h2);
    if (HAS_POOL) {
        int gn = batchp[n];
        int bin = gn - s_gf;
        if (bin < 4) atomicAdd(&s_pool[bin * 32 + lane], h2);
        else         atomicAdd(&poolraw[gn * 32 + lane], h2);
    }
    __syncthreads();
    if (tid < 32)       atomicAdd(&g_stats[sl_out * 64 + tid], s_sum[tid]);
    else if (tid < 64)  atomicAdd(&g_stats[sl_out * 64 + tid], s_sq[tid - 32]);
    else if (HAS_POOL && tid < 192) {
        int bi = tid - 64;                 // 0..127
        float v = s_pool[bi];
        int gg = s_gf + (bi >> 5);
        if (v != 0.f && gg < N_GRAPHS) atomicAdd(&poolraw[gg * 32 + (bi & 31)], v);
    }
}

// ---------------- final fused layer: gather + BN-fold + 32->32->128 --------
__global__ void __launch_bounds__(512) gin_last_fused_kernel(
    const float* __restrict__ xin, float* __restrict__ outp,
    const float* __restrict__ w1, const float* __restrict__ b1,
    const float* __restrict__ w2L, const float* __restrict__ b2L,
    int sl_in, const float* __restrict__ gamma, const float* __restrict__ beta)
{
    __shared__ float s_w1[1024];
    __shared__ float wLs[HID * DIM_IN];
    __shared__ float sa[32], sb[32], s_b1[32];
    int tid = threadIdx.x, lane = tid & 31, wrp = tid >> 5;

    for (int i = tid; i < 1024; i += 512) s_w1[i] = w1[i];
    for (int i = tid; i < HID * DIM_IN; i += 512) wLs[i] = w2L[i];
    if (tid < 32) {
        s_b1[tid] = b1[tid];
        float s = g_stats[sl_in * 64 + tid];
        float q = g_stats[sl_in * 64 + 32 + tid];
        const float invn = 1.f / (float)N_NODES;
        float m = s * invn;
        float v = fmaxf(q * invn - m * m, 0.f);
        float a = gamma[tid] * rsqrtf(v + BN_EPS);
        sa[tid] = a;
        sb[tid] = beta[tid] - a * m;
    }
    __syncthreads();

    int n = blockIdx.x * 16 + wrp;
    int start = g_rowptr[n], end = g_rowptr[n + 1];

    float t = gather_sum(xin, n, start, end, lane);
    t = sa[lane] * t + (float)(end - start + 1) * sb[lane];

    float h1 = s_b1[lane];
    #pragma unroll
    for (int k = 0; k < 32; k++) h1 += __shfl_sync(FULLMASK, t, k) * s_w1[k * 32 + lane];
    h1 = fmaxf(h1, 0.f);

    float o0 = b2L[lane], o1 = b2L[32 + lane], o2 = b2L[64 + lane], o3 = b2L[96 + lane];
    #pragma unroll
    for (int k = 0; k < 32; k++) {
        float hk = __shfl_sync(FULLMASK, h1, k);
        const float* wr = &wLs[k * 128];
        o0 += hk * wr[lane];
        o1 += hk * wr[32 + lane];
        o2 += hk * wr[64 + lane];
        o3 += hk * wr[96 + lane];
    }
    float* orow = outp + (long long)n * 128;
    orow[lane]      = fmaxf(o0, 0.f);
    orow[32 + lane] = fmaxf(o1, 0.f);
    orow[64 + lane] = fmaxf(o2, 0.f);
    orow[96 + lane] = fmaxf(o3, 0.f);
}

// ---------------- BN apply (final encoder output only) ---------------------
__global__ void __launch_bounds__(256) bn_out_kernel(
    const float* __restrict__ pre, float* __restrict__ outp, int sl,
    const float* __restrict__ gamma, const float* __restrict__ beta)
{
    __shared__ float sa[32], sb[32];
    if (threadIdx.x < 32) {
        float s = g_stats[sl * 64 + threadIdx.x];
        float q = g_stats[sl * 64 + 32 + threadIdx.x];
        const float invn = 1.f / (float)N_NODES;
        float m = s * invn;
        float v = fmaxf(q * invn - m * m, 0.f);
        float a = gamma[threadIdx.x] * rsqrtf(v + BN_EPS);
        sa[threadIdx.x] = a;
        sb[threadIdx.x] = beta[threadIdx.x] - a * m;
    }
    __syncthreads();
    int i = blockIdx.x * 256 + threadIdx.x;     // float4 index; exact coverage
    int f0 = (i & 7) * 4;
    float4 v4 = ((const float4*)pre)[i];
    v4.x = sa[f0]     * v4.x + sb[f0];
    v4.y = sa[f0 + 1] * v4.y + sb[f0 + 1];
    v4.z = sa[f0 + 2] * v4.z + sb[f0 + 2];
    v4.w = sa[f0 + 3] * v4.w + sb[f0 + 3];
    ((float4*)outp)[i] = v4;
}

// ---------------- pool finalize: affine of raw pool, all 5 layers ----------
__global__ void __launch_bounds__(256) pool_finalize_kernel(
    float* __restrict__ dst, const float* __restrict__ gamma,
    const float* __restrict__ beta)
{
    int i = blockIdx.x * 256 + threadIdx.x;     // 0 .. 512*160
    if (i >= N_GRAPHS * 160) return;
    int g = i / 160, r = i - g * 160;
    int layer = r >> 5, f = r & 31;
    float s = g_stats[layer * 64 + f];
    float q = g_stats[layer * 64 + 32 + f];
    const float invn = 1.f / (float)N_NODES;
    float m = s * invn;
    float v = fmaxf(q * invn - m * m, 0.f);
    float a = gamma[layer * 32 + f] * rsqrtf(v + BN_EPS);
    float b = beta[layer * 32 + f] - a * m;
    int cnt = g_goff[g + 1] - g_goff[g];
    dst[g * 160 + layer * 32 + f] =
        a * g_poolraw[(layer * N_GRAPHS + g) * 32 + f] + (float)cnt * b;
}

// ---------------- launch ---------------------------------------------------
extern "C" void kernel_launch(void* const* d_in, const int* in_sizes, int n_in,
                              void* d_out, int out_size) {
    const float* x        = (const float*)d_in[0];
    const int*   ei       = (const int*)d_in[1];
    const int*   batch    = (const int*)d_in[2];
    const float* e0_w1    = (const float*)d_in[3];
    const float* e0_b1    = (const float*)d_in[4];
    const float* e0_w2    = (const float*)d_in[5];
    const float* e0_b2    = (const float*)d_in[6];
    const float* enc_w1   = (const float*)d_in[7];
    const float* enc_b1   = (const float*)d_in[8];
    const float* enc_w2   = (const float*)d_in[9];
    const float* enc_b2   = (const float*)d_in[10];
    const float* enc_gamma= (const float*)d_in[11];
    const float* enc_beta = (const float*)d_in[12];
    const float* dec_w1   = (const float*)d_in[13];
    const float* dec_b1   = (const float*)d_in[14];
    const float* dec_w2   = (const float*)d_in[15];
    const float* dec_b2   = (const float*)d_in[16];
    const float* dec_w2_last = (const float*)d_in[17];
    const float* dec_b2_last = (const float*)d_in[18];
    const float* dec_gamma= (const float*)d_in[19];
    const float* dec_beta = (const float*)d_in[20];
    float* out = (float*)d_out;

    const int* srcp = ei;
    const int* dstp = ei + N_EDGES;

    float *pA, *pC, *pXP, *pPool;
    cudaGetSymbolAddress((void**)&pA,    g_bufA);
    cudaGetSymbolAddress((void**)&pC,    g_bufC);
    cudaGetSymbolAddress((void**)&pXP,   g_xp);
    cudaGetSymbolAddress((void**)&pPool, g_poolraw);

    static int s_setup_done = 0;
    static cudaStream_t s2 = 0;
    static cudaEvent_t evF = 0, evJ = 0;
    static int s_have_stream = 0;
    if (!s_setup_done) {
        cudaFuncSetAttribute(proj_kernel,
            cudaFuncAttributeMaxDynamicSharedMemorySize, PROJ_SMEM);
        if (cudaStreamCreateWithFlags(&s2, cudaStreamNonBlocking) == cudaSuccess &&
            cudaEventCreateWithFlags(&evF, cudaEventDisableTiming) == cudaSuccess &&
            cudaEventCreateWithFlags(&evJ, cudaEventDisableTiming) == cudaSuccess)
            s_have_stream = 1;
        s_setup_done = 1;
    }

    // ----- proj forked onto side stream, overlapped with CSR build -----
    if (s_have_stream) {
        cudaEventRecord(evF, 0);
        cudaStreamWaitEvent(s2, evF, 0);
        proj_kernel<<<1563, 256, PROJ_SMEM, s2>>>(x, e0_w1);
        cudaEventRecord(evJ, s2);
    } else {
        proj_kernel<<<1563, 256, PROJ_SMEM>>>(x, e0_w1);
    }

    // CSR build (main stream)
    init_kernel<<<782, 256>>>();
    hist_kernel<<<6250, 256>>>(dstp);
    scan_block_kernel<<<SCAN_BLOCKS, 1024>>>();
    scan_tops_kernel<<<1, 256>>>();
    scan_add_kernel<<<SCAN_BLOCKS, 1024>>>();
    offsets_kernel<<<3, 256>>>(batch);
    permute_kernel<<<6250, 256>>>(srcp, dstp);

    if (s_have_stream) cudaStreamWaitEvent(0, evJ, 0);   // join: gin0 needs xp

    float* cur = pXP;
    float* nxt = pA;
    float* alt = pC;

    // ----- encoder (BN folded into next layer; pool folded into gin) -----
    gin_fused_kernel<false, false, true><<<12500, 512>>>(cur, nxt, nullptr,
        e0_b1, e0_w2, e0_b2, 0, nullptr, nullptr, 0, batch, pPool);
    cur = nxt; nxt = alt; alt = cur;   // cur=A, nxt=C
    for (int L = 1; L < 5; L++) {
        gin_fused_kernel<true, true, true><<<12500, 512>>>(cur, nxt,
            enc_w1 + (L - 1) * 1024, enc_b1 + (L - 1) * 32,
            enc_w2 + (L - 1) * 1024, enc_b2 + (L - 1) * 32,
            L - 1, enc_gamma + (L - 1) * 32, enc_beta + (L - 1) * 32, L,
            batch, pPool + L * N_GRAPHS * 32);
        { float* t = cur; cur = nxt; nxt = t; }
    }
    bn_out_kernel<<<6250, 256>>>(cur, out + ENC_OFF, 4, enc_gamma + 4 * 32, enc_beta + 4 * 32);
    pool_finalize_kernel<<<(N_GRAPHS * 160 + 255) / 256, 256>>>(
        out + GLOB_OFF, enc_gamma, enc_beta);

    // ----- decoder -----
    for (int L = 0; L < 4; L++) {
        const float* gI = (L == 0) ? (enc_gamma + 4 * 32) : (dec_gamma + (L - 1) * 32);
        const float* bI = (L == 0) ? (enc_beta  + 4 * 32) : (dec_beta  + (L - 1) * 32);
        int slin = (L == 0) ? 4 : (4 + L);
        gin_fused_kernel<true, true, false><<<12500, 512>>>(cur, nxt,
            dec_w1 + L * 1024, dec_b1 + L * 32,
            dec_w2 + L * 1024, dec_b2 + L * 32,
            slin, gI, bI, 5 + L, nullptr, nullptr);
        { float* t = cur; cur = nxt; nxt = t; }
    }
    gin_last_fused_kernel<<<12500, 512>>>(cur, out + DEC_OFF,
        dec_w1 + 4 * 1024, dec_b1 + 4 * 32, dec_w2_last, dec_b2_last,
        8, dec_gamma + 3 * 32, dec_beta + 3 * 32);
}

// round 14
// speedup vs baseline: 1.0708x; 1.0141x over previous
#include <cuda_runtime.h>
#include <cuda_bf16.h>

#define N_NODES   200000
#define N_EDGES   6400000
#define N_GRAPHS  512
#define DIM_IN    128
#define HID       32
#define BN_EPS    1e-5f

#define ENC_OFF   0
#define DEC_OFF   (N_NODES * HID)                     // 6,400,000
#define GLOB_OFF  (N_NODES * HID + N_NODES * DIM_IN)  // 32,000,000

#define FULLMASK  0xffffffffu
#define SCAN_BLOCKS 196

// ---------------- scratch (device globals; no cudaMalloc allowed) ----------
__device__ int   g_cnt[N_NODES];
__device__ int   g_rowptr[N_NODES + 1];
__device__ int   g_cursor[N_NODES];
__device__ int   g_col[N_EDGES];
__device__ int   g_bsum[SCAN_BLOCKS];
__device__ int   g_boff[SCAN_BLOCKS];
__device__ int   g_goff[N_GRAPHS + 1];
__device__ float g_stats[10 * 64];                    // per layer: sum[32], sumsq[32]
__device__ float g_poolraw[5 * N_GRAPHS * 32];        // raw per-graph sums, enc layers
__device__ __align__(16) float g_xp[N_NODES * HID];   // projected layer-0 input
__device__ __align__(16) float g_bufA[N_NODES * HID]; // ping
__device__ __align__(16) float g_bufC[N_NODES * HID]; // pong

// ---------------- setup kernels --------------------------------------------
__global__ void init_kernel() {
    int i = blockIdx.x * 256 + threadIdx.x;
    if (i < N_NODES) g_cnt[i] = 0;
    if (i < 10 * 64) g_stats[i] = 0.f;
    if (i < 5 * N_GRAPHS * 32) g_poolraw[i] = 0.f;
}

__global__ void hist_kernel(const int* __restrict__ dst) {
    int e4 = blockIdx.x * 256 + threadIdx.x;   // int4 index; 6250*256*4 == N_EDGES
    int4 d = ((const int4*)dst)[e4];
    atomicAdd(&g_cnt[d.x], 1);
    atomicAdd(&g_cnt[d.y], 1);
    atomicAdd(&g_cnt[d.z], 1);
    atomicAdd(&g_cnt[d.w], 1);
}

// --- 3-phase exclusive scan of g_cnt -> g_rowptr / g_cursor ----------------
__global__ void scan_block_kernel() {      // SCAN_BLOCKS x 1024
    __shared__ int wtot[32];
    int tid = threadIdx.x, lane = tid & 31, wid = tid >> 5;
    int i = blockIdx.x * 1024 + tid;
    int v = (i < N_NODES) ? g_cnt[i] : 0;
    int incl = v;
    #pragma unroll
    for (int off = 1; off < 32; off <<= 1) {
        int t = __shfl_up_sync(FULLMASK, incl, off);
        if (lane >= off) incl += t;
    }
    if (lane == 31) wtot[wid] = incl;
    __syncthreads();
    if (wid == 0) {
        int wv = wtot[lane];
        #pragma unroll
        for (int off = 1; off < 32; off <<= 1) {
            int t = __shfl_up_sync(FULLMASK, wv, off);
            if (lane >= off) wv += t;
        }
        wtot[lane] = wv;
    }
    __syncthreads();
    int excl = (wid ? wtot[wid - 1] : 0) + incl - v;
    if (i < N_NODES) g_rowptr[i] = excl;
    if (tid == 1023) g_bsum[blockIdx.x] = wtot[31];
}

// scan of block sums (threads 0..1023, data 0..195) + graph offsets fused
__global__ void scan_tops_offsets_kernel(const int* __restrict__ batch) {
    __shared__ int wt[32];
    int tid = threadIdx.x, lane = tid & 31, wid = tid >> 5;

    // --- graph offsets (independent work, no sync interaction) ---
    if (tid <= N_GRAPHS) {
        if (tid == N_GRAPHS) g_goff[tid] = N_NODES;
        else {
            int lo = 0, hi = N_NODES;
            while (lo < hi) {
                int mid = (lo + hi) >> 1;
                if (batch[mid] < tid) lo = mid + 1; else hi = mid;
            }
            g_goff[tid] = lo;
        }
    }

    // --- tops scan ---
    int v = (tid < SCAN_BLOCKS) ? g_bsum[tid] : 0;
    int incl = v;
    #pragma unroll
    for (int off = 1; off < 32; off <<= 1) {
        int t = __shfl_up_sync(FULLMASK, incl, off);
        if (lane >= off) incl += t;
    }
    if (lane == 31) wt[wid] = incl;
    __syncthreads();
    if (wid == 0) {
        int wv = wt[lane];
        #pragma unroll
        for (int off = 1; off < 32; off <<= 1) {
            int t = __shfl_up_sync(FULLMASK, wv, off);
            if (lane >= off) wv += t;
        }
        wt[lane] = wv;
    }
    __syncthreads();
    int excl = (wid ? wt[wid - 1] : 0) + incl - v;
    if (tid < SCAN_BLOCKS) g_boff[tid] = excl;
}

__global__ void scan_add_kernel() {        // SCAN_BLOCKS x 1024
    int i = blockIdx.x * 1024 + threadIdx.x;
    if (i < N_NODES) {
        int r = g_rowptr[i] + g_boff[blockIdx.x];
        g_rowptr[i] = r;
        g_cursor[i] = r;
    }
    if (i == 0) g_rowptr[N_NODES] = N_EDGES;
}

__global__ void permute_kernel(const int* __restrict__ src, const int* __restrict__ dst) {
    int e4 = blockIdx.x * 256 + threadIdx.x;   // int4 index; 6250*256*4 == N_EDGES
    int4 s = ((const int4*)src)[e4];
    int4 d = ((const int4*)dst)[e4];
    g_col[atomicAdd(&g_cursor[d.x], 1)] = s.x;
    g_col[atomicAdd(&g_cursor[d.y], 1)] = s.y;
    g_col[atomicAdd(&g_cursor[d.z], 1)] = s.z;
    g_col[atomicAdd(&g_cursor[d.w], 1)] = s.w;
}

// ---------------- projection: xp = x @ e0_w1 (128 -> 32), GEMM-tiled -------
#define PROJ_SMEM ((128 * 132 + 128 * 32) * 4)
__global__ void __launch_bounds__(256) proj_kernel(const float* __restrict__ x,
                                                   const float* __restrict__ w1) {
    extern __shared__ float sm[];
    float* s_x = sm;               // stride 132 over k-rows
    float* s_w = sm + 128 * 132;
    int tid = threadIdx.x, lane = tid & 31, wrp = tid >> 5;
    int n0 = blockIdx.x * 128;

    for (int i = tid; i < 4096; i += 256) s_w[i] = w1[i];
    #pragma unroll
    for (int r = wrp; r < 128; r += 8) {
        int nn = n0 + r;
        const float* xr = x + (long long)nn * 128;
        #pragma unroll
        for (int c0 = 0; c0 < 128; c0 += 32) {
            float v = (nn < N_NODES) ? xr[c0 + lane] : 0.f;
            s_x[(c0 + lane) * 132 + r] = v;
        }
    }
    __syncthreads();

    int nb = (tid & 31) * 4, fb = (tid >> 5) * 4;
    float h[16];
    #pragma unroll
    for (int i = 0; i < 16; i++) h[i] = 0.f;
    #pragma unroll 4
    for (int k = 0; k < 128; k++) {
        float4 xv = *(const float4*)&s_x[k * 132 + nb];
        float4 wv = *(const float4*)&s_w[k * 32 + fb];
        h[0]  += xv.x * wv.x; h[1]  += xv.x * wv.y; h[2]  += xv.x * wv.z; h[3]  += xv.x * wv.w;
        h[4]  += xv.y * wv.x; h[5]  += xv.y * wv.y; h[6]  += xv.y * wv.z; h[7]  += xv.y * wv.w;
        h[8]  += xv.z * wv.x; h[9]  += xv.z * wv.y; h[10] += xv.z * wv.z; h[11] += xv.z * wv.w;
        h[12] += xv.w * wv.x; h[13] += xv.w * wv.y; h[14] += xv.w * wv.z; h[15] += xv.w * wv.w;
    }
    __syncthreads();
    #pragma unroll
    for (int ni = 0; ni < 4; ni++)
        #pragma unroll
        for (int fi = 0; fi < 4; fi++)
            s_x[(nb + ni) * 33 + fb + fi] = h[ni * 4 + fi];
    __syncthreads();
    #pragma unroll
    for (int r = wrp; r < 128; r += 8) {
        int nn = n0 + r;
        if (nn < N_NODES) g_xp[nn * 32 + lane] = s_x[r * 33 + lane];
    }
}

// ---------------- vectorized gather helper (proven in R9) ------------------
__device__ __forceinline__ float gather_sum(const float* __restrict__ xin,
                                            int n, int start, int end,
                                            int lane) {
    const float4* x4 = (const float4*)xin;
    int c = lane & 7;
    int g = lane >> 3;
    float4 acc = make_float4(0.f, 0.f, 0.f, 0.f);
    if (g == 0) acc = x4[n * 8 + c];                 // self term, counted once
    for (int b0 = start; b0 < end; b0 += 32) {
        int nrem = end - b0;                         // >= 1
        int li = (lane < nrem) ? lane : 0;
        int idx = g_col[b0 + li];
        #pragma unroll
        for (int k = 0; k < 32; k += 4) {
            if (k < nrem) {
                int j = __shfl_sync(FULLMASK, idx, k + g);
                float4 v = x4[j * 8 + c];
                if (k + g < nrem) {
                    acc.x += v.x; acc.y += v.y; acc.z += v.z; acc.w += v.w;
                }
            }
        }
    }
    acc.x += __shfl_xor_sync(FULLMASK, acc.x, 8);
    acc.y += __shfl_xor_sync(FULLMASK, acc.y, 8);
    acc.z += __shfl_xor_sync(FULLMASK, acc.z, 8);
    acc.w += __shfl_xor_sync(FULLMASK, acc.w, 8);
    acc.x += __shfl_xor_sync(FULLMASK, acc.x, 16);
    acc.y += __shfl_xor_sync(FULLMASK, acc.y, 16);
    acc.z += __shfl_xor_sync(FULLMASK, acc.z, 16);
    acc.w += __shfl_xor_sync(FULLMASK, acc.w, 16);
    int srcl = lane >> 2;
    float tx = __shfl_sync(FULLMASK, acc.x, srcl);
    float ty = __shfl_sync(FULLMASK, acc.y, srcl);
    float tz = __shfl_sync(FULLMASK, acc.z, srcl);
    float tw = __shfl_sync(FULLMASK, acc.w, srcl);
    int comp = lane & 3;
    float t = (comp == 0) ? tx : (comp == 1) ? ty : (comp == 2) ? tz : tw;
    return t;
}

// ---------------- fused GIN: gather + BN-fold + MLP + tree stats (+pool) ---
// 512 threads = 16 nodes/block; stats/pool via STS tree, NO smem atomics
template <bool HAS_BN, bool APPLY_W1, bool HAS_POOL>
__global__ void __launch_bounds__(512) gin_fused_kernel(
    const float* __restrict__ xin, float* __restrict__ outp,
    const float* __restrict__ w1, const float* __restrict__ b1,
    const float* __restrict__ w2, const float* __restrict__ b2,
    int sl_in, const float* __restrict__ gamma, const float* __restrict__ beta,
    int sl_out, const int* __restrict__ batchp, float* __restrict__ poolraw)
{
    __shared__ float s_w1[1024], s_w2[1024];
    __shared__ float sa[32], sb[32], s_b1[32], s_b2[32];
    __shared__ float s_part[16 * 32];
    __shared__ int   s_gidx[16];
    int tid = threadIdx.x, lane = tid & 31, wrp = tid >> 5;

    if (APPLY_W1) for (int i = tid; i < 1024; i += 512) s_w1[i] = w1[i];
    for (int i = tid; i < 1024; i += 512) s_w2[i] = w2[i];
    if (tid < 32) {
        s_b1[tid] = b1[tid]; s_b2[tid] = b2[tid];
        if (HAS_BN) {
            float s = g_stats[sl_in * 64 + tid];
            float q = g_stats[sl_in * 64 + 32 + tid];
            const float invn = 1.f / (float)N_NODES;
            float m = s * invn;
            float v = fmaxf(q * invn - m * m, 0.f);
            float a = gamma[tid] * rsqrtf(v + BN_EPS);
            sa[tid] = a;
            sb[tid] = beta[tid] - a * m;
        }
    }
    __syncthreads();

    int n = blockIdx.x * 16 + wrp;
    int start = g_rowptr[n], end = g_rowptr[n + 1];

    float t = gather_sum(xin, n, start, end, lane);
    if (HAS_BN) t = sa[lane] * t + (float)(end - start + 1) * sb[lane];

    float h1;
    if (APPLY_W1) {
        h1 = s_b1[lane];
        #pragma unroll
        for (int k = 0; k < 32; k++) h1 += __shfl_sync(FULLMASK, t, k) * s_w1[k * 32 + lane];
    } else {
        h1 = t + s_b1[lane];
    }
    h1 = fmaxf(h1, 0.f);

    float h2 = s_b2[lane];
    #pragma unroll
    for (int k = 0; k < 32; k++) h2 += __shfl_sync(FULLMASK, h1, k) * s_w2[k * 32 + lane];
    h2 = fmaxf(h2, 0.f);

    outp[n * 32 + lane] = h2;

    // stage per-warp vector (plain STS, conflict-free) + graph index
    s_part[wrp * 32 + lane] = h2;
    if (HAS_POOL && lane == 0) s_gidx[wrp] = batchp[n];
    __syncthreads();

    // warp 0 tree-reduces: stats (+pool bins), few global atomics
    if (wrp == 0) {
        float asum = 0.f, asq = 0.f;
        float rb0 = 0.f, rb1 = 0.f, rb2 = 0.f, rb3 = 0.f;
        int gf = HAS_POOL ? s_gidx[0] : 0;
        #pragma unroll
        for (int w = 0; w < 16; w++) {
            float v = s_part[w * 32 + lane];
            asum += v; asq += v * v;
            if (HAS_POOL) {
                int bin = s_gidx[w] - gf;
                if (bin == 0)      rb0 += v;
                else if (bin == 1) rb1 += v;
                else if (bin == 2) rb2 += v;
                else if (bin == 3) rb3 += v;
                else atomicAdd(&poolraw[s_gidx[w] * 32 + lane], v);
            }
        }
        atomicAdd(&g_stats[sl_out * 64 + lane], asum);
        atomicAdd(&g_stats[sl_out * 64 + 32 + lane], asq);
        if (HAS_POOL) {
            atomicAdd(&poolraw[gf * 32 + lane], rb0);
            if (rb1 != 0.f && gf + 1 < N_GRAPHS) atomicAdd(&poolraw[(gf + 1) * 32 + lane], rb1);
            if (rb2 != 0.f && gf + 2 < N_GRAPHS) atomicAdd(&poolraw[(gf + 2) * 32 + lane], rb2);
            if (rb3 != 0.f && gf + 3 < N_GRAPHS) atomicAdd(&poolraw[(gf + 3) * 32 + lane], rb3);
        }
    }
}

// ---------------- final fused layer: gather + BN-fold + 32->32->128 --------
__global__ void __launch_bounds__(512) gin_last_fused_kernel(
    const float* __restrict__ xin, float* __restrict__ outp,
    const float* __restrict__ w1, const float* __restrict__ b1,
    const float* __restrict__ w2L, const float* __restrict__ b2L,
    int sl_in, const float* __restrict__ gamma, const float* __restrict__ beta)
{
    __shared__ float s_w1[1024];
    __shared__ float wLs[HID * DIM_IN];
    __shared__ float sa[32], sb[32], s_b1[32];
    int tid = threadIdx.x, lane = tid & 31, wrp = tid >> 5;

    for (int i = tid; i < 1024; i += 512) s_w1[i] = w1[i];
    for (int i = tid; i < HID * DIM_IN; i += 512) wLs[i] = w2L[i];
    if (tid < 32) {
        s_b1[tid] = b1[tid];
        float s = g_stats[sl_in * 64 + tid];
        float q = g_stats[sl_in * 64 + 32 + tid];
        const float invn = 1.f / (float)N_NODES;
        float m = s * invn;
        float v = fmaxf(q * invn - m * m, 0.f);
        float a = gamma[tid] * rsqrtf(v + BN_EPS);
        sa[tid] = a;
        sb[tid] = beta[tid] - a * m;
    }
    __syncthreads();

    int n = blockIdx.x * 16 + wrp;
    int start = g_rowptr[n], end = g_rowptr[n + 1];

    float t = gather_sum(xin, n, start, end, lane);
    t = sa[lane] * t + (float)(end - start + 1) * sb[lane];

    float h1 = s_b1[lane];
    #pragma unroll
    for (int k = 0; k < 32; k++) h1 += __shfl_sync(FULLMASK, t, k) * s_w1[k * 32 + lane];
    h1 = fmaxf(h1, 0.f);

    float o0 = b2L[lane], o1 = b2L[32 + lane], o2 = b2L[64 + lane], o3 = b2L[96 + lane];
    #pragma unroll
    for (int k = 0; k < 32; k++) {
        float hk = __shfl_sync(FULLMASK, h1, k);
        const float* wr = &wLs[k * 128];
        o0 += hk * wr[lane];
        o1 += hk * wr[32 + lane];
        o2 += hk * wr[64 + lane];
        o3 += hk * wr[96 + lane];
    }
    float* orow = outp + (long long)n * 128;
    orow[lane]      = fmaxf(o0, 0.f);
    orow[32 + lane] = fmaxf(o1, 0.f);
    orow[64 + lane] = fmaxf(o2, 0.f);
    orow[96 + lane] = fmaxf(o3, 0.f);
}

// ---------------- BN apply (final encoder output only) ---------------------
__global__ void __launch_bounds__(256) bn_out_kernel(
    const float* __restrict__ pre, float* __restrict__ outp, int sl,
    const float* __restrict__ gamma, const float* __restrict__ beta)
{
    __shared__ float sa[32], sb[32];
    if (threadIdx.x < 32) {
        float s = g_stats[sl * 64 + threadIdx.x];
        float q = g_stats[sl * 64 + 32 + threadIdx.x];
        const float invn = 1.f / (float)N_NODES;
        float m = s * invn;
        float v = fmaxf(q * invn - m * m, 0.f);
        float a = gamma[threadIdx.x] * rsqrtf(v + BN_EPS);
        sa[threadIdx.x] = a;
        sb[threadIdx.x] = beta[threadIdx.x] - a * m;
    }
    __syncthreads();
    int i = blockIdx.x * 256 + threadIdx.x;     // float4 index; exact coverage
    int f0 = (i & 7) * 4;
    float4 v4 = ((const float4*)pre)[i];
    v4.x = sa[f0]     * v4.x + sb[f0];
    v4.y = sa[f0 + 1] * v4.y + sb[f0 + 1];
    v4.z = sa[f0 + 2] * v4.z + sb[f0 + 2];
    v4.w = sa[f0 + 3] * v4.w + sb[f0 + 3];
    ((float4*)outp)[i] = v4;
}

// ---------------- pool finalize: affine of raw pool, all 5 layers ----------
__global__ void __launch_bounds__(256) pool_finalize_kernel(
    float* __restrict__ dst, const float* __restrict__ gamma,
    const float* __restrict__ beta)
{
    int i = blockIdx.x * 256 + threadIdx.x;     // 0 .. 512*160
    if (i >= N_GRAPHS * 160) return;
    int g = i / 160, r = i - g * 160;
    int layer = r >> 5, f = r & 31;
    float s = g_stats[layer * 64 + f];
    float q = g_stats[layer * 64 + 32 + f];
    const float invn = 1.f / (float)N_NODES;
    float m = s * invn;
    float v = fmaxf(q * invn - m * m, 0.f);
    float a = gamma[layer * 32 + f] * rsqrtf(v + BN_EPS);
    float b = beta[layer * 32 + f] - a * m;
    int cnt = g_goff[g + 1] - g_goff[g];
    dst[g * 160 + layer * 32 + f] =
        a * g_poolraw[(layer * N_GRAPHS + g) * 32 + f] + (float)cnt * b;
}

// ---------------- launch ---------------------------------------------------
extern "C" void kernel_launch(void* const* d_in, const int* in_sizes, int n_in,
                              void* d_out, int out_size) {
    const float* x        = (const float*)d_in[0];
    const int*   ei       = (const int*)d_in[1];
    const int*   batch    = (const int*)d_in[2];
    const float* e0_w1    = (const float*)d_in[3];
    const float* e0_b1    = (const float*)d_in[4];
    const float* e0_w2    = (const float*)d_in[5];
    const float* e0_b2    = (const float*)d_in[6];
    const float* enc_w1   = (const float*)d_in[7];
    const float* enc_b1   = (const float*)d_in[8];
    const float* enc_w2   = (const float*)d_in[9];
    const float* enc_b2   = (const float*)d_in[10];
    const float* enc_gamma= (const float*)d_in[11];
    const float* enc_beta = (const float*)d_in[12];
    const float* dec_w1   = (const float*)d_in[13];
    const float* dec_b1   = (const float*)d_in[14];
    const float* dec_w2   = (const float*)d_in[15];
    const float* dec_b2   = (const float*)d_in[16];
    const float* dec_w2_last = (const float*)d_in[17];
    const float* dec_b2_last = (const float*)d_in[18];
    const float* dec_gamma= (const float*)d_in[19];
    const float* dec_beta = (const float*)d_in[20];
    float* out = (float*)d_out;

    const int* srcp = ei;
    const int* dstp = ei + N_EDGES;

    float *pA, *pC, *pXP, *pPool;
    cudaGetSymbolAddress((void**)&pA,    g_bufA);
    cudaGetSymbolAddress((void**)&pC,    g_bufC);
    cudaGetSymbolAddress((void**)&pXP,   g_xp);
    cudaGetSymbolAddress((void**)&pPool, g_poolraw);

    static int s_setup_done = 0;
    static cudaStream_t s2 = 0;
    static cudaEvent_t evF = 0, evJ = 0, evE = 0, evJ2 = 0;
    static int s_have_stream = 0;
    if (!s_setup_done) {
        cudaFuncSetAttribute(proj_kernel,
            cudaFuncAttributeMaxDynamicSharedMemorySize, PROJ_SMEM);
        if (cudaStreamCreateWithFlags(&s2, cudaStreamNonBlocking) == cudaSuccess &&
            cudaEventCreateWithFlags(&evF,  cudaEventDisableTiming) == cudaSuccess &&
            cudaEventCreateWithFlags(&evJ,  cudaEventDisableTiming) == cudaSuccess &&
            cudaEventCreateWithFlags(&evE,  cudaEventDisableTiming) == cudaSuccess &&
            cudaEventCreateWithFlags(&evJ2, cudaEventDisableTiming) == cudaSuccess)
            s_have_stream = 1;
        s_setup_done = 1;
    }

    // ----- proj forked onto side stream, overlapped with CSR build -----
    if (s_have_stream) {
        cudaEventRecord(evF, 0);
        cudaStreamWaitEvent(s2, evF, 0);
        proj_kernel<<<1563, 256, PROJ_SMEM, s2>>>(x, e0_w1);
        cudaEventRecord(evJ, s2);
    } else {
        proj_kernel<<<1563, 256, PROJ_SMEM>>>(x, e0_w1);
    }

    // CSR build (main stream)
    init_kernel<<<782, 256>>>();
    hist_kernel<<<6250, 256>>>(dstp);
    scan_block_kernel<<<SCAN_BLOCKS, 1024>>>();
    scan_tops_offsets_kernel<<<1, 1024>>>(batch);
    scan_add_kernel<<<SCAN_BLOCKS, 1024>>>();
    permute_kernel<<<6250, 256>>>(srcp, dstp);

    if (s_have_stream) cudaStreamWaitEvent(0, evJ, 0);   // join: gin0 needs xp

    float* cur = pXP;
    float* nxt = pA;
    float* alt = pC;

    // ----- encoder (BN folded into next layer; pool folded into gin) -----
    gin_fused_kernel<false, false, true><<<12500, 512>>>(cur, nxt, nullptr,
        e0_b1, e0_w2, e0_b2, 0, nullptr, nullptr, 0, batch, pPool);
    cur = nxt; nxt = alt; alt = cur;   // cur=A, nxt=C
    for (int L = 1; L < 5; L++) {
        gin_fused_kernel<true, true, true><<<12500, 512>>>(cur, nxt,
            enc_w1 + (L - 1) * 1024, enc_b1 + (L - 1) * 32,
            enc_w2 + (L - 1) * 1024, enc_b2 + (L - 1) * 32,
            L - 1, enc_gamma + (L - 1) * 32, enc_beta + (L - 1) * 32, L,
            batch, pPool + L * N_GRAPHS * 32);
        { float* t = cur; cur = nxt; nxt = t; }
    }

    // ----- bn_out + pool_finalize forked, overlapped with decoder -----
    if (s_have_stream) {
        cudaEventRecord(evE, 0);
        cudaStreamWaitEvent(s2, evE, 0);
        bn_out_kernel<<<6250, 256, 0, s2>>>(cur, out + ENC_OFF, 4,
            enc_gamma + 4 * 32, enc_beta + 4 * 32);
        pool_finalize_kernel<<<(N_GRAPHS * 160 + 255) / 256, 256, 0, s2>>>(
            out + GLOB_OFF, enc_gamma, enc_beta);
        cudaEventRecord(evJ2, s2);
    } else {
        bn_out_kernel<<<6250, 256>>>(cur, out + ENC_OFF, 4,
            enc_gamma + 4 * 32, enc_beta + 4 * 32);
        pool_finalize_kernel<<<(N_GRAPHS * 160 + 255) / 256, 256>>>(
            out + GLOB_OFF, enc_gamma, enc_beta);
    }

    // ----- decoder -----
    for (int L = 0; L < 4; L++) {
        const float* gI = (L == 0) ? (enc_gamma + 4 * 32) : (dec_gamma + (L - 1) * 32);
        const float* bI = (L == 0) ? (enc_beta  + 4 * 32) : (dec_beta  + (L - 1) * 32);
        int slin = (L == 0) ? 4 : (4 + L);
        gin_fused_kernel<true, true, false><<<12500, 512>>>(cur, nxt,
            dec_w1 + L * 1024, dec_b1 + L * 32,
            dec_w2 + L * 1024, dec_b2 + L * 32,
            slin, gI, bI, 5 + L, nullptr, nullptr);
        { float* t = cur; cur = nxt; nxt = t; }
    }
    gin_last_fused_kernel<<<12500, 512>>>(cur, out + DEC_OFF,
        dec_w1 + 4 * 1024, dec_b1 + 4 * 32, dec_w2_last, dec_b2_last,
        8, dec_gamma + 3 * 32, dec_beta + 3 * 32);

    if (s_have_stream) cudaStreamWaitEvent(0, evJ2, 0);  // join side stream
}

// round 15
// speedup vs baseline: 1.1245x; 1.0501x over previous
#include <cuda_runtime.h>
#include <cuda_bf16.h>

#define N_NODES   200000
#define N_EDGES   6400000
#define N_GRAPHS  512
#define DIM_IN    128
#define HID       32
#define BN_EPS    1e-5f

#define ENC_OFF   0
#define DEC_OFF   (N_NODES * HID)                     // 6,400,000
#define GLOB_OFF  (N_NODES * HID + N_NODES * DIM_IN)  // 32,000,000

#define FULLMASK  0xffffffffu
#define SCAN_BLOCKS 196

// ---------------- scratch (device globals; no cudaMalloc allowed) ----------
__device__ int   g_cnt[N_NODES];
__device__ int   g_rowptr[N_NODES + 1];
__device__ int   g_cursor[N_NODES];
__device__ int   g_col[N_EDGES];
__device__ int   g_bsum[SCAN_BLOCKS];
__device__ int   g_boff[SCAN_BLOCKS];
__device__ int   g_goff[N_GRAPHS + 1];
__device__ float g_stats[10 * 64];                    // per layer: sum[32], sumsq[32]
__device__ float g_poolraw[5 * N_GRAPHS * 32];        // raw per-graph sums, enc layers
__device__ __align__(16) float g_xp[N_NODES * HID];   // projected layer-0 input
__device__ __align__(16) float g_bufA[N_NODES * HID]; // ping
__device__ __align__(16) float g_bufC[N_NODES * HID]; // pong

// ---------------- setup kernels --------------------------------------------
__global__ void init_kernel() {
    int i = blockIdx.x * 256 + threadIdx.x;
    if (i < N_NODES) g_cnt[i] = 0;
    if (i < 10 * 64) g_stats[i] = 0.f;
    if (i < 5 * N_GRAPHS * 32) g_poolraw[i] = 0.f;
}

__global__ void hist_kernel(const int* __restrict__ dst) {
    int e4 = blockIdx.x * 256 + threadIdx.x;   // int4 index; 6250*256*4 == N_EDGES
    int4 d = ((const int4*)dst)[e4];
    atomicAdd(&g_cnt[d.x], 1);
    atomicAdd(&g_cnt[d.y], 1);
    atomicAdd(&g_cnt[d.z], 1);
    atomicAdd(&g_cnt[d.w], 1);
}

// --- 3-phase exclusive scan of g_cnt -> g_rowptr / g_cursor ----------------
__global__ void scan_block_kernel() {      // SCAN_BLOCKS x 1024
    __shared__ int wtot[32];
    int tid = threadIdx.x, lane = tid & 31, wid = tid >> 5;
    int i = blockIdx.x * 1024 + tid;
    int v = (i < N_NODES) ? g_cnt[i] : 0;
    int incl = v;
    #pragma unroll
    for (int off = 1; off < 32; off <<= 1) {
        int t = __shfl_up_sync(FULLMASK, incl, off);
        if (lane >= off) incl += t;
    }
    if (lane == 31) wtot[wid] = incl;
    __syncthreads();
    if (wid == 0) {
        int wv = wtot[lane];
        #pragma unroll
        for (int off = 1; off < 32; off <<= 1) {
            int t = __shfl_up_sync(FULLMASK, wv, off);
            if (lane >= off) wv += t;
        }
        wtot[lane] = wv;
    }
    __syncthreads();
    int excl = (wid ? wtot[wid - 1] : 0) + incl - v;
    if (i < N_NODES) g_rowptr[i] = excl;
    if (tid == 1023) g_bsum[blockIdx.x] = wtot[31];
}

// scan of block sums (threads 0..1023, data 0..195) + graph offsets fused
__global__ void scan_tops_offsets_kernel(const int* __restrict__ batch) {
    __shared__ int wt[32];
    int tid = threadIdx.x, lane = tid & 31, wid = tid >> 5;

    if (tid <= N_GRAPHS) {
        if (tid == N_GRAPHS) g_goff[tid] = N_NODES;
        else {
            int lo = 0, hi = N_NODES;
            while (lo < hi) {
                int mid = (lo + hi) >> 1;
                if (batch[mid] < tid) lo = mid + 1; else hi = mid;
            }
            g_goff[tid] = lo;
        }
    }

    int v = (tid < SCAN_BLOCKS) ? g_bsum[tid] : 0;
    int incl = v;
    #pragma unroll
    for (int off = 1; off < 32; off <<= 1) {
        int t = __shfl_up_sync(FULLMASK, incl, off);
        if (lane >= off) incl += t;
    }
    if (lane == 31) wt[wid] = incl;
    __syncthreads();
    if (wid == 0) {
        int wv = wt[lane];
        #pragma unroll
        for (int off = 1; off < 32; off <<= 1) {
            int t = __shfl_up_sync(FULLMASK, wv, off);
            if (lane >= off) wv += t;
        }
        wt[lane] = wv;
    }
    __syncthreads();
    int excl = (wid ? wt[wid - 1] : 0) + incl - v;
    if (tid < SCAN_BLOCKS) g_boff[tid] = excl;
}

__global__ void scan_add_kernel() {        // SCAN_BLOCKS x 1024
    int i = blockIdx.x * 1024 + threadIdx.x;
    if (i < N_NODES) {
        int r = g_rowptr[i] + g_boff[blockIdx.x];
        g_rowptr[i] = r;
        g_cursor[i] = r;
    }
    if (i == 0) g_rowptr[N_NODES] = N_EDGES;
}

__global__ void permute_kernel(const int* __restrict__ src, const int* __restrict__ dst) {
    int e4 = blockIdx.x * 256 + threadIdx.x;   // int4 index; 6250*256*4 == N_EDGES
    int4 s = ((const int4*)src)[e4];
    int4 d = ((const int4*)dst)[e4];
    g_col[atomicAdd(&g_cursor[d.x], 1)] = s.x;
    g_col[atomicAdd(&g_cursor[d.y], 1)] = s.y;
    g_col[atomicAdd(&g_cursor[d.z], 1)] = s.z;
    g_col[atomicAdd(&g_cursor[d.w], 1)] = s.w;
}

// ---------------- projection: xp = x @ e0_w1 (128 -> 32), GEMM-tiled -------
#define PROJ_SMEM ((128 * 132 + 128 * 32) * 4)
__global__ void __launch_bounds__(256) proj_kernel(const float* __restrict__ x,
                                                   const float* __restrict__ w1) {
    extern __shared__ float sm[];
    float* s_x = sm;               // stride 132 over k-rows
    float* s_w = sm + 128 * 132;
    int tid = threadIdx.x, lane = tid & 31, wrp = tid >> 5;
    int n0 = blockIdx.x * 128;

    for (int i = tid; i < 4096; i += 256) s_w[i] = w1[i];
    #pragma unroll
    for (int r = wrp; r < 128; r += 8) {
        int nn = n0 + r;
        const float* xr = x + (long long)nn * 128;
        #pragma unroll
        for (int c0 = 0; c0 < 128; c0 += 32) {
            float v = (nn < N_NODES) ? xr[c0 + lane] : 0.f;
            s_x[(c0 + lane) * 132 + r] = v;
        }
    }
    __syncthreads();

    int nb = (tid & 31) * 4, fb = (tid >> 5) * 4;
    float h[16];
    #pragma unroll
    for (int i = 0; i < 16; i++) h[i] = 0.f;
    #pragma unroll 4
    for (int k = 0; k < 128; k++) {
        float4 xv = *(const float4*)&s_x[k * 132 + nb];
        float4 wv = *(const float4*)&s_w[k * 32 + fb];
        h[0]  += xv.x * wv.x; h[1]  += xv.x * wv.y; h[2]  += xv.x * wv.z; h[3]  += xv.x * wv.w;
        h[4]  += xv.y * wv.x; h[5]  += xv.y * wv.y; h[6]  += xv.y * wv.z; h[7]  += xv.y * wv.w;
        h[8]  += xv.z * wv.x; h[9]  += xv.z * wv.y; h[10] += xv.z * wv.z; h[11] += xv.z * wv.w;
        h[12] += xv.w * wv.x; h[13] += xv.w * wv.y; h[14] += xv.w * wv.z; h[15] += xv.w * wv.w;
    }
    __syncthreads();
    #pragma unroll
    for (int ni = 0; ni < 4; ni++)
        #pragma unroll
        for (int fi = 0; fi < 4; fi++)
            s_x[(nb + ni) * 33 + fb + fi] = h[ni * 4 + fi];
    __syncthreads();
    #pragma unroll
    for (int r = wrp; r < 128; r += 8) {
        int nn = n0 + r;
        if (nn < N_NODES) g_xp[nn * 32 + lane] = s_x[r * 33 + lane];
    }
}

// ---------------- vectorized gather helper (proven in R9) ------------------
__device__ __forceinline__ float gather_sum(const float* __restrict__ xin,
                                            int n, int start, int end,
                                            int lane) {
    const float4* x4 = (const float4*)xin;
    int c = lane & 7;
    int g = lane >> 3;
    float4 acc = make_float4(0.f, 0.f, 0.f, 0.f);
    if (g == 0) acc = x4[n * 8 + c];                 // self term, counted once
    for (int b0 = start; b0 < end; b0 += 32) {
        int nrem = end - b0;                         // >= 1
        int li = (lane < nrem) ? lane : 0;
        int idx = g_col[b0 + li];
        #pragma unroll
        for (int k = 0; k < 32; k += 4) {
            if (k < nrem) {
                int j = __shfl_sync(FULLMASK, idx, k + g);
                float4 v = x4[j * 8 + c];
                if (k + g < nrem) {
                    acc.x += v.x; acc.y += v.y; acc.z += v.z; acc.w += v.w;
                }
            }
        }
    }
    acc.x += __shfl_xor_sync(FULLMASK, acc.x, 8);
    acc.y += __shfl_xor_sync(FULLMASK, acc.y, 8);
    acc.z += __shfl_xor_sync(FULLMASK, acc.z, 8);
    acc.w += __shfl_xor_sync(FULLMASK, acc.w, 8);
    acc.x += __shfl_xor_sync(FULLMASK, acc.x, 16);
    acc.y += __shfl_xor_sync(FULLMASK, acc.y, 16);
    acc.z += __shfl_xor_sync(FULLMASK, acc.z, 16);
    acc.w += __shfl_xor_sync(FULLMASK, acc.w, 16);
    int srcl = lane >> 2;
    float tx = __shfl_sync(FULLMASK, acc.x, srcl);
    float ty = __shfl_sync(FULLMASK, acc.y, srcl);
    float tz = __shfl_sync(FULLMASK, acc.z, srcl);
    float tw = __shfl_sync(FULLMASK, acc.w, srcl);
    int comp = lane & 3;
    float t = (comp == 0) ? tx : (comp == 1) ? ty : (comp == 2) ? tz : tw;
    return t;
}

// ---------------- fused GIN: gather + BN-fold + L1-weight MLP + tree stats -
// Weights read directly via coalesced LDG (L1-resident across blocks on an SM
// within a launch) — no smem staging, no per-block L2 weight traffic.
template <bool HAS_BN, bool APPLY_W1, bool HAS_POOL>
__global__ void __launch_bounds__(512) gin_fused_kernel(
    const float* __restrict__ xin, float* __restrict__ outp,
    const float* __restrict__ w1, const float* __restrict__ b1,
    const float* __restrict__ w2, const float* __restrict__ b2,
    int sl_in, const float* __restrict__ gamma, const float* __restrict__ beta,
    int sl_out, const int* __restrict__ batchp, float* __restrict__ poolraw)
{
    __shared__ float sa[32], sb[32];
    __shared__ float s_part[16 * 32];
    __shared__ int   s_gidx[16];
    int tid = threadIdx.x, lane = tid & 31, wrp = tid >> 5;

    if (HAS_BN) {
        if (tid < 32) {
            float s = g_stats[sl_in * 64 + tid];
            float q = g_stats[sl_in * 64 + 32 + tid];
            const float invn = 1.f / (float)N_NODES;
            float m = s * invn;
            float v = fmaxf(q * invn - m * m, 0.f);
            float a = gamma[tid] * rsqrtf(v + BN_EPS);
            sa[tid] = a;
            sb[tid] = beta[tid] - a * m;
        }
        __syncthreads();
    }

    int n = blockIdx.x * 16 + wrp;
    int start = g_rowptr[n], end = g_rowptr[n + 1];

    float t = gather_sum(xin, n, start, end, lane);
    if (HAS_BN) t = sa[lane] * t + (float)(end - start + 1) * sb[lane];

    float h1;
    if (APPLY_W1) {
        h1 = b1[lane];
        #pragma unroll
        for (int k = 0; k < 32; k++) h1 += __shfl_sync(FULLMASK, t, k) * w1[k * 32 + lane];
    } else {
        h1 = t + b1[lane];
    }
    h1 = fmaxf(h1, 0.f);

    float h2 = b2[lane];
    #pragma unroll
    for (int k = 0; k < 32; k++) h2 += __shfl_sync(FULLMASK, h1, k) * w2[k * 32 + lane];
    h2 = fmaxf(h2, 0.f);

    outp[n * 32 + lane] = h2;

    // stage per-warp vector (plain STS, conflict-free) + graph index
    s_part[wrp * 32 + lane] = h2;
    if (HAS_POOL && lane == 0) s_gidx[wrp] = batchp[n];
    __syncthreads();

    // warp 0 tree-reduces: stats (+pool bins), few global atomics
    if (wrp == 0) {
        float asum = 0.f, asq = 0.f;
        float rb0 = 0.f, rb1 = 0.f, rb2 = 0.f, rb3 = 0.f;
        int gf = HAS_POOL ? s_gidx[0] : 0;
        #pragma unroll
        for (int w = 0; w < 16; w++) {
            float v = s_part[w * 32 + lane];
            asum += v; asq += v * v;
            if (HAS_POOL) {
                int bin = s_gidx[w] - gf;
                if (bin == 0)      rb0 += v;
                else if (bin == 1) rb1 += v;
                else if (bin == 2) rb2 += v;
                else if (bin == 3) rb3 += v;
                else atomicAdd(&poolraw[s_gidx[w] * 32 + lane], v);
            }
        }
        atomicAdd(&g_stats[sl_out * 64 + lane], asum);
        atomicAdd(&g_stats[sl_out * 64 + 32 + lane], asq);
        if (HAS_POOL) {
            atomicAdd(&poolraw[gf * 32 + lane], rb0);
            if (rb1 != 0.f && gf + 1 < N_GRAPHS) atomicAdd(&poolraw[(gf + 1) * 32 + lane], rb1);
            if (rb2 != 0.f && gf + 2 < N_GRAPHS) atomicAdd(&poolraw[(gf + 2) * 32 + lane], rb2);
            if (rb3 != 0.f && gf + 3 < N_GRAPHS) atomicAdd(&poolraw[(gf + 3) * 32 + lane], rb3);
        }
    }
}

// ---------------- final fused layer: gather + BN-fold + 32->32->128 --------
__global__ void __launch_bounds__(512) gin_last_fused_kernel(
    const float* __restrict__ xin, float* __restrict__ outp,
    const float* __restrict__ w1, const float* __restrict__ b1,
    const float* __restrict__ w2L, const float* __restrict__ b2L,
    int sl_in, const float* __restrict__ gamma, const float* __restrict__ beta)
{
    __shared__ float sa[32], sb[32];
    int tid = threadIdx.x, lane = tid & 31, wrp = tid >> 5;

    if (tid < 32) {
        float s = g_stats[sl_in * 64 + tid];
        float q = g_stats[sl_in * 64 + 32 + tid];
        const float invn = 1.f / (float)N_NODES;
        float m = s * invn;
        float v = fmaxf(q * invn - m * m, 0.f);
        float a = gamma[tid] * rsqrtf(v + BN_EPS);
        sa[tid] = a;
        sb[tid] = beta[tid] - a * m;
    }
    __syncthreads();

    int n = blockIdx.x * 16 + wrp;
    int start = g_rowptr[n], end = g_rowptr[n + 1];

    float t = gather_sum(xin, n, start, end, lane);
    t = sa[lane] * t + (float)(end - start + 1) * sb[lane];

    float h1 = b1[lane];
    #pragma unroll
    for (int k = 0; k < 32; k++) h1 += __shfl_sync(FULLMASK, t, k) * w1[k * 32 + lane];
    h1 = fmaxf(h1, 0.f);

    float o0 = b2L[lane], o1 = b2L[32 + lane], o2 = b2L[64 + lane], o3 = b2L[96 + lane];
    #pragma unroll
    for (int k = 0; k < 32; k++) {
        float hk = __shfl_sync(FULLMASK, h1, k);
        const float* wr = w2L + k * 128;
        o0 += hk * wr[lane];
        o1 += hk * wr[32 + lane];
        o2 += hk * wr[64 + lane];
        o3 += hk * wr[96 + lane];
    }
    float* orow = outp + (long long)n * 128;
    orow[lane]      = fmaxf(o0, 0.f);
    orow[32 + lane] = fmaxf(o1, 0.f);
    orow[64 + lane] = fmaxf(o2, 0.f);
    orow[96 + lane] = fmaxf(o3, 0.f);
}

// ---------------- BN apply (final encoder output only) ---------------------
__global__ void __launch_bounds__(256) bn_out_kernel(
    const float* __restrict__ pre, float* __restrict__ outp, int sl,
    const float* __restrict__ gamma, const float* __restrict__ beta)
{
    __shared__ float sa[32], sb[32];
    if (threadIdx.x < 32) {
        float s = g_stats[sl * 64 + threadIdx.x];
        float q = g_stats[sl * 64 + 32 + threadIdx.x];
        const float invn = 1.f / (float)N_NODES;
        float m = s * invn;
        float v = fmaxf(q * invn - m * m, 0.f);
        float a = gamma[threadIdx.x] * rsqrtf(v + BN_EPS);
        sa[threadIdx.x] = a;
        sb[threadIdx.x] = beta[threadIdx.x] - a * m;
    }
    __syncthreads();
    int i = blockIdx.x * 256 + threadIdx.x;     // float4 index; exact coverage
    int f0 = (i & 7) * 4;
    float4 v4 = ((const float4*)pre)[i];
    v4.x = sa[f0]     * v4.x + sb[f0];
    v4.y = sa[f0 + 1] * v4.y + sb[f0 + 1];
    v4.z = sa[f0 + 2] * v4.z + sb[f0 + 2];
    v4.w = sa[f0 + 3] * v4.w + sb[f0 + 3];
    ((float4*)outp)[i] = v4;
}

// ---------------- pool finalize: affine of raw pool, all 5 layers ----------
__global__ void __launch_bounds__(256) pool_finalize_kernel(
    float* __restrict__ dst, const float* __restrict__ gamma,
    const float* __restrict__ beta)
{
    int i = blockIdx.x * 256 + threadIdx.x;     // 0 .. 512*160
    if (i >= N_GRAPHS * 160) return;
    int g = i / 160, r = i - g * 160;
    int layer = r >> 5, f = r & 31;
    float s = g_stats[layer * 64 + f];
    float q = g_stats[layer * 64 + 32 + f];
    const float invn = 1.f / (float)N_NODES;
    float m = s * invn;
    float v = fmaxf(q * invn - m * m, 0.f);
    float a = gamma[layer * 32 + f] * rsqrtf(v + BN_EPS);
    float b = beta[layer * 32 + f] - a * m;
    int cnt = g_goff[g + 1] - g_goff[g];
    dst[g * 160 + layer * 32 + f] =
        a * g_poolraw[(layer * N_GRAPHS + g) * 32 + f] + (float)cnt * b;
}

// ---------------- launch ---------------------------------------------------
extern "C" void kernel_launch(void* const* d_in, const int* in_sizes, int n_in,
                              void* d_out, int out_size) {
    const float* x        = (const float*)d_in[0];
    const int*   ei       = (const int*)d_in[1];
    const int*   batch    = (const int*)d_in[2];
    const float* e0_w1    = (const float*)d_in[3];
    const float* e0_b1    = (const float*)d_in[4];
    const float* e0_w2    = (const float*)d_in[5];
    const float* e0_b2    = (const float*)d_in[6];
    const float* enc_w1   = (const float*)d_in[7];
    const float* enc_b1   = (const float*)d_in[8];
    const float* enc_w2   = (const float*)d_in[9];
    const float* enc_b2   = (const float*)d_in[10];
    const float* enc_gamma= (const float*)d_in[11];
    const float* enc_beta = (const float*)d_in[12];
    const float* dec_w1   = (const float*)d_in[13];
    const float* dec_b1   = (const float*)d_in[14];
    const float* dec_w2   = (const float*)d_in[15];
    const float* dec_b2   = (const float*)d_in[16];
    const float* dec_w2_last = (const float*)d_in[17];
    const float* dec_b2_last = (const float*)d_in[18];
    const float* dec_gamma= (const float*)d_in[19];
    const float* dec_beta = (const float*)d_in[20];
    float* out = (float*)d_out;

    const int* srcp = ei;
    const int* dstp = ei + N_EDGES;

    float *pA, *pC, *pXP, *pPool;
    cudaGetSymbolAddress((void**)&pA,    g_bufA);
    cudaGetSymbolAddress((void**)&pC,    g_bufC);
    cudaGetSymbolAddress((void**)&pXP,   g_xp);
    cudaGetSymbolAddress((void**)&pPool, g_poolraw);

    static int s_setup_done = 0;
    static cudaStream_t s2 = 0;
    static cudaEvent_t evF = 0, evJ = 0, evE = 0, evJ2 = 0;
    static int s_have_stream = 0;
    if (!s_setup_done) {
        cudaFuncSetAttribute(proj_kernel,
            cudaFuncAttributeMaxDynamicSharedMemorySize, PROJ_SMEM);
        if (cudaStreamCreateWithFlags(&s2, cudaStreamNonBlocking) == cudaSuccess &&
            cudaEventCreateWithFlags(&evF,  cudaEventDisableTiming) == cudaSuccess &&
            cudaEventCreateWithFlags(&evJ,  cudaEventDisableTiming) == cudaSuccess &&
            cudaEventCreateWithFlags(&evE,  cudaEventDisableTiming) == cudaSuccess &&
            cudaEventCreateWithFlags(&evJ2, cudaEventDisableTiming) == cudaSuccess)
            s_have_stream = 1;
        s_setup_done = 1;
    }

    // ----- proj forked onto side stream, overlapped with CSR build -----
    if (s_have_stream) {
        cudaEventRecord(evF, 0);
        cudaStreamWaitEvent(s2, evF, 0);
        proj_kernel<<<1563, 256, PROJ_SMEM, s2>>>(x, e0_w1);
        cudaEventRecord(evJ, s2);
    } else {
        proj_kernel<<<1563, 256, PROJ_SMEM>>>(x, e0_w1);
    }

    // CSR build (main stream)
    init_kernel<<<782, 256>>>();
    hist_kernel<<<6250, 256>>>(dstp);
    scan_block_kernel<<<SCAN_BLOCKS, 1024>>>();
    scan_tops_offsets_kernel<<<1, 1024>>>(batch);
    scan_add_kernel<<<SCAN_BLOCKS, 1024>>>();
    permute_kernel<<<6250, 256>>>(srcp, dstp);

    if (s_have_stream) cudaStreamWaitEvent(0, evJ, 0);   // join: gin0 needs xp

    float* cur = pXP;
    float* nxt = pA;
    float* alt = pC;

    // ----- encoder (BN folded into next layer; pool folded into gin) -----
    gin_fused_kernel<false, false, true><<<12500, 512>>>(cur, nxt, nullptr,
        e0_b1, e0_w2, e0_b2, 0, nullptr, nullptr, 0, batch, pPool);
    cur = nxt; nxt = alt; alt = cur;   // cur=A, nxt=C
    for (int L = 1; L < 5; L++) {
        gin_fused_kernel<true, true, true><<<12500, 512>>>(cur, nxt,
            enc_w1 + (L - 1) * 1024, enc_b1 + (L - 1) * 32,
            enc_w2 + (L - 1) * 1024, enc_b2 + (L - 1) * 32,
            L - 1, enc_gamma + (L - 1) * 32, enc_beta + (L - 1) * 32, L,
            batch, pPool + L * N_GRAPHS * 32);
        { float* t = cur; cur = nxt; nxt = t; }
    }

    // ----- bn_out + pool_finalize forked, overlapped with decoder -----
    if (s_have_stream) {
        cudaEventRecord(evE, 0);
        cudaStreamWaitEvent(s2, evE, 0);
        bn_out_kernel<<<6250, 256, 0, s2>>>(cur, out + ENC_OFF, 4,
            enc_gamma + 4 * 32, enc_beta + 4 * 32);
        pool_finalize_kernel<<<(N_GRAPHS * 160 + 255) / 256, 256, 0, s2>>>(
            out + GLOB_OFF, enc_gamma, enc_beta);
        cudaEventRecord(evJ2, s2);
    } else {
        bn_out_kernel<<<6250, 256>>>(cur, out + ENC_OFF, 4,
            enc_gamma + 4 * 32, enc_beta + 4 * 32);
        pool_finalize_kernel<<<(N_GRAPHS * 160 + 255) / 256, 256>>>(
            out + GLOB_OFF, enc_gamma, enc_beta);
    }

    // ----- decoder -----
    for (int L = 0; L < 4; L++) {
        const float* gI = (L == 0) ? (enc_gamma + 4 * 32) : (dec_gamma + (L - 1) * 32);
        const float* bI = (L == 0) ? (enc_beta  + 4 * 32) : (dec_beta  + (L - 1) * 32);
        int slin = (L == 0) ? 4 : (4 + L);
        gin_fused_kernel<true, true, false><<<12500, 512>>>(cur, nxt,
            dec_w1 + L * 1024, dec_b1 + L * 32,
            dec_w2 + L * 1024, dec_b2 + L * 32,
            slin, gI, bI, 5 + L, nullptr, nullptr);
        { float* t = cur; cur = nxt; nxt = t; }
    }
    gin_last_fused_kernel<<<12500, 512>>>(cur, out + DEC_OFF,
        dec_w1 + 4 * 1024, dec_b1 + 4 * 32, dec_w2_last, dec_b2_last,
        8, dec_gamma + 3 * 32, dec_beta + 3 * 32);

    if (s_have_stream) cudaStreamWaitEvent(0, evJ2, 0);  // join side stream
}

// round 16
// speedup vs baseline: 1.1271x; 1.0023x over previous
#include <cuda_runtime.h>
#include <cuda_bf16.h>

#define N_NODES   200000
#define N_EDGES   6400000
#define N_GRAPHS  512
#define DIM_IN    128
#define HID       32
#define BN_EPS    1e-5f

#define ENC_OFF   0
#define DEC_OFF   (N_NODES * HID)                     // 6,400,000
#define GLOB_OFF  (N_NODES * HID + N_NODES * DIM_IN)  // 32,000,000

#define FULLMASK  0xffffffffu
#define SCAN_BLOCKS 196

// ---------------- scratch (device globals; no cudaMalloc allowed) ----------
__device__ int   g_cnt[N_NODES];
__device__ int   g_rowptr[N_NODES + 1];
__device__ int   g_cursor[N_NODES];
__device__ int   g_col[N_EDGES];
__device__ int   g_bsum[SCAN_BLOCKS];
__device__ int   g_boff[SCAN_BLOCKS];
__device__ int   g_goff[N_GRAPHS + 1];
__device__ float g_stats[10 * 64];                    // per layer: sum[32], sumsq[32]
__device__ float g_poolraw[5 * N_GRAPHS * 32];        // raw per-graph sums, enc layers
__device__ __align__(16) float g_xp[N_NODES * HID];   // projected layer-0 input
__device__ __align__(16) float g_bufA[N_NODES * HID]; // ping
__device__ __align__(16) float g_bufC[N_NODES * HID]; // pong

// ---------------- setup kernels --------------------------------------------
__global__ void init_kernel() {
    int i = blockIdx.x * 256 + threadIdx.x;
    if (i < N_NODES) g_cnt[i] = 0;
    if (i < 10 * 64) g_stats[i] = 0.f;
    if (i < 5 * N_GRAPHS * 32) g_poolraw[i] = 0.f;
}

__global__ void hist_kernel(const int* __restrict__ dst) {
    int e4 = blockIdx.x * 256 + threadIdx.x;   // int4 index; 6250*256*4 == N_EDGES
    int4 d = ((const int4*)dst)[e4];
    atomicAdd(&g_cnt[d.x], 1);
    atomicAdd(&g_cnt[d.y], 1);
    atomicAdd(&g_cnt[d.z], 1);
    atomicAdd(&g_cnt[d.w], 1);
}

// --- 3-phase exclusive scan of g_cnt -> g_rowptr / g_cursor ----------------
__global__ void scan_block_kernel() {      // SCAN_BLOCKS x 1024
    __shared__ int wtot[32];
    int tid = threadIdx.x, lane = tid & 31, wid = tid >> 5;
    int i = blockIdx.x * 1024 + tid;
    int v = (i < N_NODES) ? g_cnt[i] : 0;
    int incl = v;
    #pragma unroll
    for (int off = 1; off < 32; off <<= 1) {
        int t = __shfl_up_sync(FULLMASK, incl, off);
        if (lane >= off) incl += t;
    }
    if (lane == 31) wtot[wid] = incl;
    __syncthreads();
    if (wid == 0) {
        int wv = wtot[lane];
        #pragma unroll
        for (int off = 1; off < 32; off <<= 1) {
            int t = __shfl_up_sync(FULLMASK, wv, off);
            if (lane >= off) wv += t;
        }
        wtot[lane] = wv;
    }
    __syncthreads();
    int excl = (wid ? wtot[wid - 1] : 0) + incl - v;
    if (i < N_NODES) g_rowptr[i] = excl;
    if (tid == 1023) g_bsum[blockIdx.x] = wtot[31];
}

// scan of block sums (threads 0..1023, data 0..195) + graph offsets fused
__global__ void scan_tops_offsets_kernel(const int* __restrict__ batch) {
    __shared__ int wt[32];
    int tid = threadIdx.x, lane = tid & 31, wid = tid >> 5;

    if (tid <= N_GRAPHS) {
        if (tid == N_GRAPHS) g_goff[tid] = N_NODES;
        else {
            int lo = 0, hi = N_NODES;
            while (lo < hi) {
                int mid = (lo + hi) >> 1;
                if (batch[mid] < tid) lo = mid + 1; else hi = mid;
            }
            g_goff[tid] = lo;
        }
    }

    int v = (tid < SCAN_BLOCKS) ? g_bsum[tid] : 0;
    int incl = v;
    #pragma unroll
    for (int off = 1; off < 32; off <<= 1) {
        int t = __shfl_up_sync(FULLMASK, incl, off);
        if (lane >= off) incl += t;
    }
    if (lane == 31) wt[wid] = incl;
    __syncthreads();
    if (wid == 0) {
        int wv = wt[lane];
        #pragma unroll
        for (int off = 1; off < 32; off <<= 1) {
            int t = __shfl_up_sync(FULLMASK, wv, off);
            if (lane >= off) wv += t;
        }
        wt[lane] = wv;
    }
    __syncthreads();
    int excl = (wid ? wt[wid - 1] : 0) + incl - v;
    if (tid < SCAN_BLOCKS) g_boff[tid] = excl;
}

__global__ void scan_add_kernel() {        // SCAN_BLOCKS x 1024
    int i = blockIdx.x * 1024 + threadIdx.x;
    if (i < N_NODES) {
        int r = g_rowptr[i] + g_boff[blockIdx.x];
        g_rowptr[i] = r;
        g_cursor[i] = r;
    }
    if (i == 0) g_rowptr[N_NODES] = N_EDGES;
}

__global__ void permute_kernel(const int* __restrict__ src, const int* __restrict__ dst) {
    int e4 = blockIdx.x * 256 + threadIdx.x;   // int4 index; 6250*256*4 == N_EDGES
    int4 s = ((const int4*)src)[e4];
    int4 d = ((const int4*)dst)[e4];
    g_col[atomicAdd(&g_cursor[d.x], 1)] = s.x;
    g_col[atomicAdd(&g_cursor[d.y], 1)] = s.y;
    g_col[atomicAdd(&g_cursor[d.z], 1)] = s.z;
    g_col[atomicAdd(&g_cursor[d.w], 1)] = s.w;
}

// ---------------- projection: xp = x @ e0_w1 (128 -> 32), GEMM-tiled -------
#define PROJ_SMEM ((128 * 132 + 128 * 32) * 4)
__global__ void __launch_bounds__(256) proj_kernel(const float* __restrict__ x,
                                                   const float* __restrict__ w1) {
    extern __shared__ float sm[];
    float* s_x = sm;               // stride 132 over k-rows
    float* s_w = sm + 128 * 132;
    int tid = threadIdx.x, lane = tid & 31, wrp = tid >> 5;
    int n0 = blockIdx.x * 128;

    for (int i = tid; i < 4096; i += 256) s_w[i] = w1[i];
    #pragma unroll
    for (int r = wrp; r < 128; r += 8) {
        int nn = n0 + r;
        const float* xr = x + (long long)nn * 128;
        #pragma unroll
        for (int c0 = 0; c0 < 128; c0 += 32) {
            float v = (nn < N_NODES) ? xr[c0 + lane] : 0.f;
            s_x[(c0 + lane) * 132 + r] = v;
        }
    }
    __syncthreads();

    int nb = (tid & 31) * 4, fb = (tid >> 5) * 4;
    float h[16];
    #pragma unroll
    for (int i = 0; i < 16; i++) h[i] = 0.f;
    #pragma unroll 4
    for (int k = 0; k < 128; k++) {
        float4 xv = *(const float4*)&s_x[k * 132 + nb];
        float4 wv = *(const float4*)&s_w[k * 32 + fb];
        h[0]  += xv.x * wv.x; h[1]  += xv.x * wv.y; h[2]  += xv.x * wv.z; h[3]  += xv.x * wv.w;
        h[4]  += xv.y * wv.x; h[5]  += xv.y * wv.y; h[6]  += xv.y * wv.z; h[7]  += xv.y * wv.w;
        h[8]  += xv.z * wv.x; h[9]  += xv.z * wv.y; h[10] += xv.z * wv.z; h[11] += xv.z * wv.w;
        h[12] += xv.w * wv.x; h[13] += xv.w * wv.y; h[14] += xv.w * wv.z; h[15] += xv.w * wv.w;
    }
    __syncthreads();
    #pragma unroll
    for (int ni = 0; ni < 4; ni++)
        #pragma unroll
        for (int fi = 0; fi < 4; fi++)
            s_x[(nb + ni) * 33 + fb + fi] = h[ni * 4 + fi];
    __syncthreads();
    #pragma unroll
    for (int r = wrp; r < 128; r += 8) {
        int nn = n0 + r;
        if (nn < N_NODES) g_xp[nn * 32 + lane] = s_x[r * 33 + lane];
    }
}

// ---------------- vectorized gather helper (R16: per-load predication) -----
// lane = (c = lane&7 feature-chunk, g = lane>>3 neighbor-subgroup)
// Predicating the LDG itself means tail blocks issue NO wasted 128B row reads.
__device__ __forceinline__ float gather_sum(const float* __restrict__ xin,
                                            int n, int start, int end,
                                            int lane) {
    const float4* x4 = (const float4*)xin;
    int c = lane & 7;
    int g = lane >> 3;
    float4 acc = make_float4(0.f, 0.f, 0.f, 0.f);
    if (g == 0) acc = x4[n * 8 + c];                 // self term, counted once
    for (int b0 = start; b0 < end; b0 += 32) {
        int nrem = end - b0;                         // >= 1
        int li = (lane < nrem) ? lane : 0;
        int idx = g_col[b0 + li];
        #pragma unroll
        for (int k = 0; k < 32; k += 4) {
            if (k < nrem) {
                int j = __shfl_sync(FULLMASK, idx, k + g);   // uniform: all lanes exec
                if (k + g < nrem) {                          // predicated LDG + FADD
                    float4 v = x4[j * 8 + c];
                    acc.x += v.x; acc.y += v.y; acc.z += v.z; acc.w += v.w;
                }
            }
        }
    }
    acc.x += __shfl_xor_sync(FULLMASK, acc.x, 8);
    acc.y += __shfl_xor_sync(FULLMASK, acc.y, 8);
    acc.z += __shfl_xor_sync(FULLMASK, acc.z, 8);
    acc.w += __shfl_xor_sync(FULLMASK, acc.w, 8);
    acc.x += __shfl_xor_sync(FULLMASK, acc.x, 16);
    acc.y += __shfl_xor_sync(FULLMASK, acc.y, 16);
    acc.z += __shfl_xor_sync(FULLMASK, acc.z, 16);
    acc.w += __shfl_xor_sync(FULLMASK, acc.w, 16);
    int srcl = lane >> 2;
    float tx = __shfl_sync(FULLMASK, acc.x, srcl);
    float ty = __shfl_sync(FULLMASK, acc.y, srcl);
    float tz = __shfl_sync(FULLMASK, acc.z, srcl);
    float tw = __shfl_sync(FULLMASK, acc.w, srcl);
    int comp = lane & 3;
    float t = (comp == 0) ? tx : (comp == 1) ? ty : (comp == 2) ? tz : tw;
    return t;
}

// ---------------- fused GIN: gather + BN-fold + L1-weight MLP + tree stats -
template <bool HAS_BN, bool APPLY_W1, bool HAS_POOL>
__global__ void __launch_bounds__(512) gin_fused_kernel(
    const float* __restrict__ xin, float* __restrict__ outp,
    const float* __restrict__ w1, const float* __restrict__ b1,
    const float* __restrict__ w2, const float* __restrict__ b2,
    int sl_in, const float* __restrict__ gamma, const float* __restrict__ beta,
    int sl_out, const int* __restrict__ batchp, float* __restrict__ poolraw)
{
    __shared__ float sa[32], sb[32];
    __shared__ float s_part[16 * 32];
    __shared__ int   s_gidx[16];
    int tid = threadIdx.x, lane = tid & 31, wrp = tid >> 5;

    if (HAS_BN) {
        if (tid < 32) {
            float s = g_stats[sl_in * 64 + tid];
            float q = g_stats[sl_in * 64 + 32 + tid];
            const float invn = 1.f / (float)N_NODES;
            float m = s * invn;
            float v = fmaxf(q * invn - m * m, 0.f);
            float a = gamma[tid] * rsqrtf(v + BN_EPS);
            sa[tid] = a;
            sb[tid] = beta[tid] - a * m;
        }
        __syncthreads();
    }

    int n = blockIdx.x * 16 + wrp;
    int start = g_rowptr[n], end = g_rowptr[n + 1];

    float t = gather_sum(xin, n, start, end, lane);
    if (HAS_BN) t = sa[lane] * t + (float)(end - start + 1) * sb[lane];

    float h1;
    if (APPLY_W1) {
        h1 = b1[lane];
        #pragma unroll
        for (int k = 0; k < 32; k++) h1 += __shfl_sync(FULLMASK, t, k) * w1[k * 32 + lane];
    } else {
        h1 = t + b1[lane];
    }
    h1 = fmaxf(h1, 0.f);

    float h2 = b2[lane];
    #pragma unroll
    for (int k = 0; k < 32; k++) h2 += __shfl_sync(FULLMASK, h1, k) * w2[k * 32 + lane];
    h2 = fmaxf(h2, 0.f);

    outp[n * 32 + lane] = h2;

    // stage per-warp vector (plain STS, conflict-free) + graph index
    s_part[wrp * 32 + lane] = h2;
    if (HAS_POOL && lane == 0) s_gidx[wrp] = batchp[n];
    __syncthreads();

    // warp 0 tree-reduces: stats (+pool bins), few global atomics
    if (wrp == 0) {
        float asum = 0.f, asq = 0.f;
        float rb0 = 0.f, rb1 = 0.f, rb2 = 0.f, rb3 = 0.f;
        int gf = HAS_POOL ? s_gidx[0] : 0;
        #pragma unroll
        for (int w = 0; w < 16; w++) {
            float v = s_part[w * 32 + lane];
            asum += v; asq += v * v;
            if (HAS_POOL) {
                int bin = s_gidx[w] - gf;
                if (bin == 0)      rb0 += v;
                else if (bin == 1) rb1 += v;
                else if (bin == 2) rb2 += v;
                else if (bin == 3) rb3 += v;
                else atomicAdd(&poolraw[s_gidx[w] * 32 + lane], v);
            }
        }
        atomicAdd(&g_stats[sl_out * 64 + lane], asum);
        atomicAdd(&g_stats[sl_out * 64 + 32 + lane], asq);
        if (HAS_POOL) {
            atomicAdd(&poolraw[gf * 32 + lane], rb0);
            if (rb1 != 0.f && gf + 1 < N_GRAPHS) atomicAdd(&poolraw[(gf + 1) * 32 + lane], rb1);
            if (rb2 != 0.f && gf + 2 < N_GRAPHS) atomicAdd(&poolraw[(gf + 2) * 32 + lane], rb2);
            if (rb3 != 0.f && gf + 3 < N_GRAPHS) atomicAdd(&poolraw[(gf + 3) * 32 + lane], rb3);
        }
    }
}

// ---------------- final fused layer: gather + BN-fold + 32->32->128 --------
__global__ void __launch_bounds__(512) gin_last_fused_kernel(
    const float* __restrict__ xin, float* __restrict__ outp,
    const float* __restrict__ w1, const float* __restrict__ b1,
    const float* __restrict__ w2L, const float* __restrict__ b2L,
    int sl_in, const float* __restrict__ gamma, const float* __restrict__ beta)
{
    __shared__ float sa[32], sb[32];
    int tid = threadIdx.x, lane = tid & 31, wrp = tid >> 5;

    if (tid < 32) {
        float s = g_stats[sl_in * 64 + tid];
        float q = g_stats[sl_in * 64 + 32 + tid];
        const float invn = 1.f / (float)N_NODES;
        float m = s * invn;
        float v = fmaxf(q * invn - m * m, 0.f);
        float a = gamma[tid] * rsqrtf(v + BN_EPS);
        sa[tid] = a;
        sb[tid] = beta[tid] - a * m;
    }
    __syncthreads();

    int n = blockIdx.x * 16 + wrp;
    int start = g_rowptr[n], end = g_rowptr[n + 1];

    float t = gather_sum(xin, n, start, end, lane);
    t = sa[lane] * t + (float)(end - start + 1) * sb[lane];

    float h1 = b1[lane];
    #pragma unroll
    for (int k = 0; k < 32; k++) h1 += __shfl_sync(FULLMASK, t, k) * w1[k * 32 + lane];
    h1 = fmaxf(h1, 0.f);

    float o0 = b2L[lane], o1 = b2L[32 + lane], o2 = b2L[64 + lane], o3 = b2L[96 + lane];
    #pragma unroll
    for (int k = 0; k < 32; k++) {
        float hk = __shfl_sync(FULLMASK, h1, k);
        const float* wr = w2L + k * 128;
        o0 += hk * wr[lane];
        o1 += hk * wr[32 + lane];
        o2 += hk * wr[64 + lane];
        o3 += hk * wr[96 + lane];
    }
    float* orow = outp + (long long)n * 128;
    orow[lane]      = fmaxf(o0, 0.f);
    orow[32 + lane] = fmaxf(o1, 0.f);
    orow[64 + lane] = fmaxf(o2, 0.f);
    orow[96 + lane] = fmaxf(o3, 0.f);
}

// ---------------- BN apply (final encoder output only) ---------------------
__global__ void __launch_bounds__(256) bn_out_kernel(
    const float* __restrict__ pre, float* __restrict__ outp, int sl,
    const float* __restrict__ gamma, const float* __restrict__ beta)
{
    __shared__ float sa[32], sb[32];
    if (threadIdx.x < 32) {
        float s = g_stats[sl * 64 + threadIdx.x];
        float q = g_stats[sl * 64 + 32 + threadIdx.x];
        const float invn = 1.f / (float)N_NODES;
        float m = s * invn;
        float v = fmaxf(q * invn - m * m, 0.f);
        float a = gamma[threadIdx.x] * rsqrtf(v + BN_EPS);
        sa[threadIdx.x] = a;
        sb[threadIdx.x] = beta[threadIdx.x] - a * m;
    }
    __syncthreads();
    int i = blockIdx.x * 256 + threadIdx.x;     // float4 index; exact coverage
    int f0 = (i & 7) * 4;
    float4 v4 = ((const float4*)pre)[i];
    v4.x = sa[f0]     * v4.x + sb[f0];
    v4.y = sa[f0 + 1] * v4.y + sb[f0 + 1];
    v4.z = sa[f0 + 2] * v4.z + sb[f0 + 2];
    v4.w = sa[f0 + 3] * v4.w + sb[f0 + 3];
    ((float4*)outp)[i] = v4;
}

// ---------------- pool finalize: affine of raw pool, all 5 layers ----------
__global__ void __launch_bounds__(256) pool_finalize_kernel(
    float* __restrict__ dst, const float* __restrict__ gamma,
    const float* __restrict__ beta)
{
    int i = blockIdx.x * 256 + threadIdx.x;     // 0 .. 512*160
    if (i >= N_GRAPHS * 160) return;
    int g = i / 160, r = i - g * 160;
    int layer = r >> 5, f = r & 31;
    float s = g_stats[layer * 64 + f];
    float q = g_stats[layer * 64 + 32 + f];
    const float invn = 1.f / (float)N_NODES;
    float m = s * invn;
    float v = fmaxf(q * invn - m * m, 0.f);
    float a = gamma[layer * 32 + f] * rsqrtf(v + BN_EPS);
    float b = beta[layer * 32 + f] - a * m;
    int cnt = g_goff[g + 1] - g_goff[g];
    dst[g * 160 + layer * 32 + f] =
        a * g_poolraw[(layer * N_GRAPHS + g) * 32 + f] + (float)cnt * b;
}

// ---------------- launch ---------------------------------------------------
extern "C" void kernel_launch(void* const* d_in, const int* in_sizes, int n_in,
                              void* d_out, int out_size) {
    const float* x        = (const float*)d_in[0];
    const int*   ei       = (const int*)d_in[1];
    const int*   batch    = (const int*)d_in[2];
    const float* e0_w1    = (const float*)d_in[3];
    const float* e0_b1    = (const float*)d_in[4];
    const float* e0_w2    = (const float*)d_in[5];
    const float* e0_b2    = (const float*)d_in[6];
    const float* enc_w1   = (const float*)d_in[7];
    const float* enc_b1   = (const float*)d_in[8];
    const float* enc_w2   = (const float*)d_in[9];
    const float* enc_b2   = (const float*)d_in[10];
    const float* enc_gamma= (const float*)d_in[11];
    const float* enc_beta = (const float*)d_in[12];
    const float* dec_w1   = (const float*)d_in[13];
    const float* dec_b1   = (const float*)d_in[14];
    const float* dec_w2   = (const float*)d_in[15];
    const float* dec_b2   = (const float*)d_in[16];
    const float* dec_w2_last = (const float*)d_in[17];
    const float* dec_b2_last = (const float*)d_in[18];
    const float* dec_gamma= (const float*)d_in[19];
    const float* dec_beta = (const float*)d_in[20];
    float* out = (float*)d_out;

    const int* srcp = ei;
    const int* dstp = ei + N_EDGES;

    float *pA, *pC, *pXP, *pPool;
    cudaGetSymbolAddress((void**)&pA,    g_bufA);
    cudaGetSymbolAddress((void**)&pC,    g_bufC);
    cudaGetSymbolAddress((void**)&pXP,   g_xp);
    cudaGetSymbolAddress((void**)&pPool, g_poolraw);

    static int s_setup_done = 0;
    static cudaStream_t s2 = 0;
    static cudaEvent_t evF = 0, evJ = 0, evE = 0, evJ2 = 0;
    static int s_have_stream = 0;
    if (!s_setup_done) {
        cudaFuncSetAttribute(proj_kernel,
            cudaFuncAttributeMaxDynamicSharedMemorySize, PROJ_SMEM);
        if (cudaStreamCreateWithFlags(&s2, cudaStreamNonBlocking) == cudaSuccess &&
            cudaEventCreateWithFlags(&evF,  cudaEventDisableTiming) == cudaSuccess &&
            cudaEventCreateWithFlags(&evJ,  cudaEventDisableTiming) == cudaSuccess &&
            cudaEventCreateWithFlags(&evE,  cudaEventDisableTiming) == cudaSuccess &&
            cudaEventCreateWithFlags(&evJ2, cudaEventDisableTiming) == cudaSuccess)
            s_have_stream = 1;
        s_setup_done = 1;
    }

    // ----- proj forked onto side stream, overlapped with CSR build -----
    if (s_have_stream) {
        cudaEventRecord(evF, 0);
        cudaStreamWaitEvent(s2, evF, 0);
        proj_kernel<<<1563, 256, PROJ_SMEM, s2>>>(x, e0_w1);
        cudaEventRecord(evJ, s2);
    } else {
        proj_kernel<<<1563, 256, PROJ_SMEM>>>(x, e0_w1);
    }

    // CSR build (main stream)
    init_kernel<<<782, 256>>>();
    hist_kernel<<<6250, 256>>>(dstp);
    scan_block_kernel<<<SCAN_BLOCKS, 1024>>>();
    scan_tops_offsets_kernel<<<1, 1024>>>(batch);
    scan_add_kernel<<<SCAN_BLOCKS, 1024>>>();
    permute_kernel<<<6250, 256>>>(srcp, dstp);

    if (s_have_stream) cudaStreamWaitEvent(0, evJ, 0);   // join: gin0 needs xp

    float* cur = pXP;
    float* nxt = pA;
    float* alt = pC;

    // ----- encoder (BN folded into next layer; pool folded into gin) -----
    gin_fused_kernel<false, false, true><<<12500, 512>>>(cur, nxt, nullptr,
        e0_b1, e0_w2, e0_b2, 0, nullptr, nullptr, 0, batch, pPool);
    cur = nxt; nxt = alt; alt = cur;   // cur=A, nxt=C
    for (int L = 1; L < 5; L++) {
        gin_fused_kernel<true, true, true><<<12500, 512>>>(cur, nxt,
            enc_w1 + (L - 1) * 1024, enc_b1 + (L - 1) * 32,
            enc_w2 + (L - 1) * 1024, enc_b2 + (L - 1) * 32,
            L - 1, enc_gamma + (L - 1) * 32, enc_beta + (L - 1) * 32, L,
            batch, pPool + L * N_GRAPHS * 32);
        { float* t = cur; cur = nxt; nxt = t; }
    }

    // ----- bn_out + pool_finalize forked, overlapped with decoder -----
    if (s_have_stream) {
        cudaEventRecord(evE, 0);
        cudaStreamWaitEvent(s2, evE, 0);
        bn_out_kernel<<<6250, 256, 0, s2>>>(cur, out + ENC_OFF, 4,
            enc_gamma + 4 * 32, enc_beta + 4 * 32);
        pool_finalize_kernel<<<(N_GRAPHS * 160 + 255) / 256, 256, 0, s2>>>(
            out + GLOB_OFF, enc_gamma, enc_beta);
        cudaEventRecord(evJ2, s2);
    } else {
        bn_out_kernel<<<6250, 256>>>(cur, out + ENC_OFF, 4,
            enc_gamma + 4 * 32, enc_beta + 4 * 32);
        pool_finalize_kernel<<<(N_GRAPHS * 160 + 255) / 256, 256>>>(
            out + GLOB_OFF, enc_gamma, enc_beta);
    }

    // ----- decoder -----
    for (int L = 0; L < 4; L++) {
        const float* gI = (L == 0) ? (enc_gamma + 4 * 32) : (dec_gamma + (L - 1) * 32);
        const float* bI = (L == 0) ? (enc_beta  + 4 * 32) : (dec_beta  + (L - 1) * 32);
        int slin = (L == 0) ? 4 : (4 + L);
        gin_fused_kernel<true, true, false><<<12500, 512>>>(cur, nxt,
            dec_w1 + L * 1024, dec_b1 + L * 32,
            dec_w2 + L * 1024, dec_b2 + L * 32,
            slin, gI, bI, 5 + L, nullptr, nullptr);
        { float* t = cur; cur = nxt; nxt = t; }
    }
    gin_last_fused_kernel<<<12500, 512>>>(cur, out + DEC_OFF,
        dec_w1 + 4 * 1024, dec_b1 + 4 * 32, dec_w2_last, dec_b2_last,
        8, dec_gamma + 3 * 32, dec_beta + 3 * 32);

    if (s_have_stream) cudaStreamWaitEvent(0, evJ2, 0);  // join side stream
}